// round 3
// baseline (speedup 1.0000x reference)
#include <cuda_runtime.h>

// Problem constants
constexpr int H   = 75;
constexpr int H3  = 225;   // 3H
constexpr int H4  = 300;   // 4H
constexpr int D2  = 150;   // 2H
constexpr int NB  = 256;   // batch
constexpr int LQ  = 64;
constexpr int LP  = 500;

constexpr int G    = 4;    // (batch,dir) items per block
constexpr int NTH  = 512;
constexpr int NBLK = (2 * NB) / G;   // 128

// Persistent device scratch (static allocation: allowed)
__device__ float g_h[2 * NB * H];          // recurrent state [dir*256+b][j]
__device__ float g_Qproj[LQ * NB * H];     // precomputed quesEnc @ WQu.T + b

__device__ __forceinline__ float sigf(float x) {
    return __fdividef(1.0f, 1.0f + __expf(-x));
}
__device__ __forceinline__ float tanhfast(float x) {
    // (e^{2x}-1)/(e^{2x}+1); correct limits at +/-inf via fdividef(., inf)=0
    return 1.0f - __fdividef(2.0f, __expf(2.0f * x) + 1.0f);
}

__global__ void init_kernel(const float* __restrict__ h0f,
                            const float* __restrict__ h0r) {
    int i = blockIdx.x * blockDim.x + threadIdx.x;
    if (i < NB * H) {
        g_h[i]          = h0f[i];
        g_h[NB * H + i] = h0r[i];
    }
}

// Qproj[m, j] = sum_k quesEnc[m, k] * WQu_w[j, k] + WQu_b[j],  m = q*B + b
__global__ void qproj_kernel(const float* __restrict__ X,
                             const float* __restrict__ W,
                             const float* __restrict__ bias) {
    int o = blockIdx.x * blockDim.x + threadIdx.x;
    if (o >= LQ * NB * H) return;
    int m = o / H;
    int j = o - m * H;
    const float2* xr = reinterpret_cast<const float2*>(X + (size_t)m * D2);
    const float2* wr = reinterpret_cast<const float2*>(W + (size_t)j * D2);
    float acc = bias[j];
#pragma unroll
    for (int k = 0; k < D2 / 2; k++) {
        float2 x = xr[k], w = wr[k];
        acc = fmaf(x.x, w.x, acc);
        acc = fmaf(x.y, w.y, acc);
    }
    g_Qproj[o] = acc;
}

__global__ __launch_bounds__(NTH, 1)
void step_kernel(int t,
                 const float* __restrict__ quesEnc,
                 const float* __restrict__ passEnc,
                 const float* __restrict__ WPu_w, const float* __restrict__ WPu_b,
                 const float* __restrict__ WPv_w, const float* __restrict__ WPv_b,
                 const float* __restrict__ Wg_w,  const float* __restrict__ Wg_b,
                 const float* __restrict__ Vt,
                 const float* __restrict__ Wih_f, const float* __restrict__ Whh_f,
                 const float* __restrict__ bih_f, const float* __restrict__ bhh_f,
                 const float* __restrict__ Wih_r, const float* __restrict__ Whh_r,
                 const float* __restrict__ bih_r, const float* __restrict__ bhh_r,
                 float* __restrict__ out) {
    __shared__ __align__(16) float sh_h[G][H + 1];
    __shared__ __align__(16) float sh_v[G][H + 1];
    __shared__ __align__(16) float sh_e[G][H + 1];
    __shared__ __align__(16) float sh_s[G][LQ];
    __shared__ __align__(16) float sh_part[2][G][LQ];
    __shared__ __align__(16) float sh_cc[G][H4 + 4];   // [p | c], row stride 1216B (16B mult)
    __shared__ __align__(16) float sh_x[G][H4 + 4];    // gated input to GRU
    __shared__ __align__(16) float sh_gi[G][H3 + 3];
    __shared__ __align__(16) float sh_gh[G][H3 + 3];

    const int tid   = threadIdx.x;
    const int item0 = blockIdx.x * G;      // all G items share dir (256 % G == 0)
    const int dir   = item0 >> 8;
    const int te    = dir ? (LP - 1 - t) : t;

    // ---- phase 0: load h, v, p ----
    for (int idx = tid; idx < G * H; idx += NTH) {
        int i = idx / H, j = idx - (idx / H) * H;
        int item = item0 + i;
        int b = item & 255;
        sh_h[i][j] = g_h[item * H + j];
        sh_v[i][j] = Vt[b * H + j];
    }
    for (int idx = tid; idx < G * D2; idx += NTH) {
        int i = idx / D2, d = idx - (idx / D2) * D2;
        int b = (item0 + i) & 255;
        sh_cc[i][d] = passEnc[((size_t)te * NB + b) * D2 + d];
    }
    __syncthreads();

    // ---- phase 1: e = WPu @ p + WPu_b + WPv @ h + WPv_b ----
    for (int idx = tid; idx < G * H; idx += NTH) {
        int i = idx / H, j = idx % H;
        float acc = WPu_b[j] + WPv_b[j];
        const float2* wu = reinterpret_cast<const float2*>(WPu_w + (size_t)j * D2);
        const float2* pp = reinterpret_cast<const float2*>(&sh_cc[i][0]);
#pragma unroll 15
        for (int k = 0; k < D2 / 2; k++) {
            float2 w = wu[k], x = pp[k];
            acc = fmaf(w.x, x.x, acc);
            acc = fmaf(w.y, x.y, acc);
        }
        const float* wv = WPv_w + (size_t)j * H;
#pragma unroll 15
        for (int k = 0; k < H; k++) acc = fmaf(wv[k], sh_h[i][k], acc);
        sh_e[i][j] = acc;
    }
    __syncthreads();

    // ---- phase 2: attention scores, 2 threads per (i,q), split j range ----
    {
        int half = tid & 1;
        int pair = tid >> 1;            // 0..255 == G*LQ
        int i = pair >> 6, q = pair & 63;
        int b = (item0 + i) & 255;
        const float* qp = g_Qproj + ((size_t)q * NB + b) * H;
        int j0 = half ? 38 : 0;
        int j1 = half ? H  : 38;
        float acc = 0.0f;
        for (int j = j0; j < j1; j++) {
            float xx = qp[j] + sh_e[i][j];
            acc = fmaf(tanhfast(xx), sh_v[i][j], acc);
        }
        sh_part[half][i][q] = acc;
    }
    __syncthreads();

    // ---- phase 3: softmax over q (warp w handles item w) ----
    {
        int wid = tid >> 5, lane = tid & 31;
        if (wid < G) {
            float v0 = sh_part[0][wid][lane]      + sh_part[1][wid][lane];
            float v1 = sh_part[0][wid][lane + 32] + sh_part[1][wid][lane + 32];
            float m = fmaxf(v0, v1);
#pragma unroll
            for (int o = 16; o > 0; o >>= 1) m = fmaxf(m, __shfl_xor_sync(0xffffffffu, m, o));
            float e0 = __expf(v0 - m), e1 = __expf(v1 - m);
            float s = e0 + e1;
#pragma unroll
            for (int o = 16; o > 0; o >>= 1) s += __shfl_xor_sync(0xffffffffu, s, o);
            float inv = __fdividef(1.0f, s);
            sh_s[wid][lane]      = e0 * inv;
            sh_s[wid][lane + 32] = e1 * inv;
        }
    }
    __syncthreads();

    // ---- phase 4: context c = a @ quesEnc_b ----
    for (int idx = tid; idx < G * D2; idx += NTH) {
        int i = idx / D2, d = idx % D2;
        int b = (item0 + i) & 255;
        const float* qe = quesEnc + (size_t)b * D2 + d;
        float acc = 0.0f;
#pragma unroll 8
        for (int q = 0; q < LQ; q++) acc = fmaf(sh_s[i][q], qe[(size_t)q * NB * D2], acc);
        sh_cc[i][D2 + d] = acc;
    }
    __syncthreads();

    // ---- phase 5: g = sigmoid(cc @ Wg.T + b); x = g * cc  (4-item accumulators) ----
    if (tid < H4) {
        int j = tid;
        float bb = Wg_b[j];
        float a0 = bb, a1 = bb, a2 = bb, a3 = bb;
        const float4* wr = reinterpret_cast<const float4*>(Wg_w + (size_t)j * H4);
        const float4* c0 = reinterpret_cast<const float4*>(&sh_cc[0][0]);
        const float4* c1 = reinterpret_cast<const float4*>(&sh_cc[1][0]);
        const float4* c2 = reinterpret_cast<const float4*>(&sh_cc[2][0]);
        const float4* c3 = reinterpret_cast<const float4*>(&sh_cc[3][0]);
#pragma unroll 5
        for (int k = 0; k < H4 / 4; k++) {
            float4 w = wr[k];
            float4 v0 = c0[k];
            a0 = fmaf(w.x, v0.x, a0); a0 = fmaf(w.y, v0.y, a0);
            a0 = fmaf(w.z, v0.z, a0); a0 = fmaf(w.w, v0.w, a0);
            float4 v1 = c1[k];
            a1 = fmaf(w.x, v1.x, a1); a1 = fmaf(w.y, v1.y, a1);
            a1 = fmaf(w.z, v1.z, a1); a1 = fmaf(w.w, v1.w, a1);
            float4 v2 = c2[k];
            a2 = fmaf(w.x, v2.x, a2); a2 = fmaf(w.y, v2.y, a2);
            a2 = fmaf(w.z, v2.z, a2); a2 = fmaf(w.w, v2.w, a2);
            float4 v3 = c3[k];
            a3 = fmaf(w.x, v3.x, a3); a3 = fmaf(w.y, v3.y, a3);
            a3 = fmaf(w.z, v3.z, a3); a3 = fmaf(w.w, v3.w, a3);
        }
        sh_x[0][j] = sigf(a0) * sh_cc[0][j];
        sh_x[1][j] = sigf(a1) * sh_cc[1][j];
        sh_x[2][j] = sigf(a2) * sh_cc[2][j];
        sh_x[3][j] = sigf(a3) * sh_cc[3][j];
    }
    __syncthreads();

    // ---- phase 6: GRU GEMVs. threads [0,225): gi = x@Wih.T ; [256,481): gh = h@Whh.T ----
    if (tid < H3) {
        int j = tid;
        const float* Wih = dir ? Wih_r : Wih_f;
        float bb = (dir ? bih_r : bih_f)[j];
        float a0 = bb, a1 = bb, a2 = bb, a3 = bb;
        const float4* wr = reinterpret_cast<const float4*>(Wih + (size_t)j * H4);
        const float4* x0 = reinterpret_cast<const float4*>(&sh_x[0][0]);
        const float4* x1 = reinterpret_cast<const float4*>(&sh_x[1][0]);
        const float4* x2 = reinterpret_cast<const float4*>(&sh_x[2][0]);
        const float4* x3 = reinterpret_cast<const float4*>(&sh_x[3][0]);
#pragma unroll 5
        for (int k = 0; k < H4 / 4; k++) {
            float4 w = wr[k];
            float4 v0 = x0[k];
            a0 = fmaf(w.x, v0.x, a0); a0 = fmaf(w.y, v0.y, a0);
            a0 = fmaf(w.z, v0.z, a0); a0 = fmaf(w.w, v0.w, a0);
            float4 v1 = x1[k];
            a1 = fmaf(w.x, v1.x, a1); a1 = fmaf(w.y, v1.y, a1);
            a1 = fmaf(w.z, v1.z, a1); a1 = fmaf(w.w, v1.w, a1);
            float4 v2 = x2[k];
            a2 = fmaf(w.x, v2.x, a2); a2 = fmaf(w.y, v2.y, a2);
            a2 = fmaf(w.z, v2.z, a2); a2 = fmaf(w.w, v2.w, a2);
            float4 v3 = x3[k];
            a3 = fmaf(w.x, v3.x, a3); a3 = fmaf(w.y, v3.y, a3);
            a3 = fmaf(w.z, v3.z, a3); a3 = fmaf(w.w, v3.w, a3);
        }
        sh_gi[0][j] = a0; sh_gi[1][j] = a1; sh_gi[2][j] = a2; sh_gi[3][j] = a3;
    } else if (tid >= 256 && tid < 256 + H3) {
        int j = tid - 256;
        const float* wr = (dir ? Whh_r : Whh_f) + (size_t)j * H;
        float bb = (dir ? bhh_r : bhh_f)[j];
        float a0 = bb, a1 = bb, a2 = bb, a3 = bb;
#pragma unroll 15
        for (int k = 0; k < H; k++) {
            float w = wr[k];
            a0 = fmaf(w, sh_h[0][k], a0);
            a1 = fmaf(w, sh_h[1][k], a1);
            a2 = fmaf(w, sh_h[2][k], a2);
            a3 = fmaf(w, sh_h[3][k], a3);
        }
        sh_gh[0][j] = a0; sh_gh[1][j] = a1; sh_gh[2][j] = a2; sh_gh[3][j] = a3;
    }
    __syncthreads();

    // ---- phase 7: GRU combine, write state + output ----
    for (int idx = tid; idx < G * H; idx += NTH) {
        int i = idx / H, j = idx % H;
        int item = item0 + i;
        int b = item & 255;
        float r = sigf(sh_gi[i][j]         + sh_gh[i][j]);
        float z = sigf(sh_gi[i][H + j]     + sh_gh[i][H + j]);
        float n = tanhfast(sh_gi[i][2 * H + j] + r * sh_gh[i][2 * H + j]);
        float hn = (1.0f - z) * n + z * sh_h[i][j];
        g_h[item * H + j] = hn;
        out[((size_t)t * NB + b) * D2 + dir * H + j] = hn;
    }
}

extern "C" void kernel_launch(void* const* d_in, const int* in_sizes, int n_in,
                              void* d_out, int out_size) {
    const float* quesEnc = (const float*)d_in[0];
    const float* passEnc = (const float*)d_in[1];
    const float* WQu_w   = (const float*)d_in[2];
    const float* WQu_b   = (const float*)d_in[3];
    const float* WPu_w   = (const float*)d_in[4];
    const float* WPu_b   = (const float*)d_in[5];
    const float* WPv_w   = (const float*)d_in[6];
    const float* WPv_b   = (const float*)d_in[7];
    const float* Wg_w    = (const float*)d_in[8];
    const float* Wg_b    = (const float*)d_in[9];
    const float* Vt      = (const float*)d_in[10];
    const float* Wih_f   = (const float*)d_in[11];
    const float* Whh_f   = (const float*)d_in[12];
    const float* bih_f   = (const float*)d_in[13];
    const float* bhh_f   = (const float*)d_in[14];
    const float* Wih_r   = (const float*)d_in[15];
    const float* Whh_r   = (const float*)d_in[16];
    const float* bih_r   = (const float*)d_in[17];
    const float* bhh_r   = (const float*)d_in[18];
    const float* h0f     = (const float*)d_in[19];
    const float* h0r     = (const float*)d_in[20];
    float* out = (float*)d_out;

    init_kernel<<<(NB * H + 255) / 256, 256>>>(h0f, h0r);
    qproj_kernel<<<(LQ * NB * H + 255) / 256, 256>>>(quesEnc, WQu_w, WQu_b);

    for (int t = 0; t < LP; t++) {
        step_kernel<<<NBLK, NTH>>>(t, quesEnc, passEnc,
                                   WPu_w, WPu_b, WPv_w, WPv_b,
                                   Wg_w, Wg_b, Vt,
                                   Wih_f, Whh_f, bih_f, bhh_f,
                                   Wih_r, Whh_r, bih_r, bhh_r,
                                   out);
    }
}

// round 6
// speedup vs baseline: 1.4586x; 1.4586x over previous
#include <cuda_runtime.h>

typedef unsigned long long ull;

// Problem constants
constexpr int H   = 75;
constexpr int H3  = 225;
constexpr int H4  = 300;
constexpr int D2  = 150;
constexpr int NB  = 256;
constexpr int LQ  = 64;
constexpr int LP  = 500;

constexpr int G    = 4;               // (batch,dir) items per block
constexpr int NTH  = 512;
constexpr int NBLK = (2 * NB) / G;    // 128 blocks, <=1 wave on 148 SMs

// Shared-memory layout (float offsets). Strides chosen for conflict-free access.
constexpr int HP   = 76;              // row stride for h/v/e
constexpr int CCS  = 308;             // row stride for cc/x (16B aligned rows)
constexpr int GIS  = 227;             // row stride for gi/gh (>= 225)

constexpr int OFF_QP   = 0;                      // [G][LQ][H] = 19200
constexpr int OFF_WHH  = OFF_QP + G * LQ * H;    // [225][75]  = 16875 (pad 16876)
constexpr int OFF_WPV  = OFF_WHH + 16876;        // [75][75]   = 5625  (pad 5628)
constexpr int OFF_H    = OFF_WPV + 5628;         // [G][HP]
constexpr int OFF_V    = OFF_H + G * HP;
constexpr int OFF_E    = OFF_V + G * HP;
constexpr int OFF_S    = OFF_E + G * HP;         // [G][LQ]
constexpr int OFF_PART = OFF_S + G * LQ;         // [2][G][LQ]
constexpr int OFF_CC   = OFF_PART + 2 * G * LQ;  // [G][CCS]  (16B aligned: 43384 % 4 == 0)
constexpr int OFF_X    = OFF_CC + G * CCS;       // [G][CCS]
constexpr int OFF_GI   = OFF_X + G * CCS;        // [G][GIS]
constexpr int OFF_GH   = OFF_GI + G * GIS;       // [G][GIS]
constexpr int SMEM_FLOATS = OFF_GH + G * GIS;    // 47664 floats = 190656 B
constexpr int SMEM_BYTES  = SMEM_FLOATS * 4;

static_assert(OFF_CC % 4 == 0, "cc rows must be 16B aligned");
static_assert(CCS % 4 == 0, "cc stride must be 16B aligned");
static_assert(SMEM_BYTES <= 232448, "smem over limit");

__device__ float g_Qproj[LQ * NB * H];   // precomputed quesEnc @ WQu.T + b (step-invariant)

// ---------- math helpers ----------
__device__ __forceinline__ float sigf(float x) {
    return __fdividef(1.0f, 1.0f + __expf(-x));
}
__device__ __forceinline__ float tanhfast(float x) {
    return 1.0f - __fdividef(2.0f, __expf(2.0f * x) + 1.0f);
}

// packed f32x2 FMA (PTX ISA 8.6, sm_100+)
__device__ __forceinline__ ull pack2(float x, float y) {
    ull r; asm("mov.b64 %0, {%1, %2};" : "=l"(r) : "f"(x), "f"(y)); return r;
}
__device__ __forceinline__ void fma2(ull& d, ull a, ull b) {
    asm("fma.rn.f32x2 %0, %1, %2, %0;" : "+l"(d) : "l"(a), "l"(b));
}
__device__ __forceinline__ float hsum2(ull a) {
    float x, y; asm("mov.b64 {%0, %1}, %2;" : "=f"(x), "=f"(y) : "l"(a));
    return x + y;
}

// ---------- Qproj precompute (runs once, tiny) ----------
__global__ void qproj_kernel(const float* __restrict__ X,
                             const float* __restrict__ W,
                             const float* __restrict__ bias) {
    int o = blockIdx.x * blockDim.x + threadIdx.x;
    if (o >= LQ * NB * H) return;
    int m = o / H;
    int j = o - m * H;
    const float2* xr = reinterpret_cast<const float2*>(X + (size_t)m * D2);
    const float2* wr = reinterpret_cast<const float2*>(W + (size_t)j * D2);
    float acc = bias[j];
#pragma unroll
    for (int k = 0; k < D2 / 2; k++) {
        float2 x = xr[k], w = wr[k];
        acc = fmaf(x.x, w.x, acc);
        acc = fmaf(x.y, w.y, acc);
    }
    g_Qproj[o] = acc;
}

// ---------- persistent kernel: full 500-step recurrence per block ----------
__global__ __launch_bounds__(NTH, 1)
void persist_kernel(const float* __restrict__ quesEnc,
                    const float* __restrict__ passEnc,
                    const float* __restrict__ WPu_w, const float* __restrict__ WPu_b,
                    const float* __restrict__ WPv_w, const float* __restrict__ WPv_b,
                    const float* __restrict__ Wg_w,  const float* __restrict__ Wg_b,
                    const float* __restrict__ Vt,
                    const float* __restrict__ Wih_f, const float* __restrict__ Whh_f,
                    const float* __restrict__ bih_f, const float* __restrict__ bhh_f,
                    const float* __restrict__ Wih_r, const float* __restrict__ Whh_r,
                    const float* __restrict__ bih_r, const float* __restrict__ bhh_r,
                    const float* __restrict__ h0f,   const float* __restrict__ h0r,
                    float* __restrict__ out) {
    extern __shared__ float sm[];
    const int tid   = threadIdx.x;
    const int item0 = blockIdx.x * G;          // all G items share dir
    const int dir   = item0 >> 8;

    // ---- one-time loads into smem ----
    {
        const float* Whh = dir ? Whh_r : Whh_f;
        for (int idx = tid; idx < H3 * H; idx += NTH) sm[OFF_WHH + idx] = Whh[idx];
        for (int idx = tid; idx < H * H; idx += NTH)  sm[OFF_WPV + idx] = WPv_w[idx];
        const float* h0 = dir ? h0r : h0f;
        for (int idx = tid; idx < G * H; idx += NTH) {
            int i = idx / H, j = idx - i * H;
            int b = (item0 + i) & 255;
            sm[OFF_H + i * HP + j] = h0[b * H + j];
            sm[OFF_V + i * HP + j] = Vt[b * H + j];
        }
        // Qproj slice: dest [i][q][j] contiguous; src g_Qproj[(q*NB+b)*H+j]
        for (int idx = tid; idx < G * LQ * H; idx += NTH) {
            int i = idx / (LQ * H);
            int r = idx - i * (LQ * H);
            int q = r / H, j = r - q * H;
            int b = (item0 + i) & 255;
            sm[OFF_QP + idx] = g_Qproj[((size_t)q * NB + b) * H + j];
        }
    }

    // ---- per-thread hoisted pointers / biases (fixed across all 500 steps) ----
    // phase 1 (300 threads): i fastest
    const int i1 = tid & 3, j1 = tid >> 2;
    const bool p1_act = (tid < G * H);
    const ull*   wpu_row = p1_act ? reinterpret_cast<const ull*>(WPu_w + (size_t)j1 * D2) : nullptr;
    const float* wpv_row = sm + OFF_WPV + j1 * H;
    const float  b_ph1   = p1_act ? (WPu_b[j1] + WPv_b[j1]) : 0.0f;

    // phase 2 (all 512 threads): 2 threads per (i,q)
    const int half = tid & 1, pair = tid >> 1;
    const int i2 = pair >> 6, q2 = pair & 63;
    const int j2lo = half ? 38 : 0;
    const int j2hi = half ? H  : 38;
    const float* qp_row = sm + OFF_QP + i2 * (LQ * H) + q2 * H;

    // phase 5 (300 threads): gate GEMV
    const bool p5_act = (tid < H4);
    const float b_g = p5_act ? Wg_b[tid] : 0.0f;
    const ulonglong2* wg_row = p5_act ? reinterpret_cast<const ulonglong2*>(Wg_w + (size_t)tid * H4) : nullptr;

    // phase 6a (225 threads): Wih GEMV  |  phase 6b (threads 256..480): Whh GEMV
    const float* Wih = dir ? Wih_r : Wih_f;
    const bool p6a = (tid < H3);
    const float b_ih = p6a ? (dir ? bih_r : bih_f)[tid] : 0.0f;
    const ulonglong2* wih_row = p6a ? reinterpret_cast<const ulonglong2*>(Wih + (size_t)tid * H4) : nullptr;
    const int jw = tid - 256;
    const bool p6b = (tid >= 256 && tid < 256 + H3);
    const float b_hh = p6b ? (dir ? bhh_r : bhh_f)[jw] : 0.0f;
    const float* whh_row = sm + OFF_WHH + (p6b ? jw : 0) * H;

    __syncthreads();

    // ================= main 500-step loop =================
    for (int t = 0; t < LP; t++) {
        const int te = dir ? (LP - 1 - t) : t;

        // ---- phase 0: load p -> cc[0..150) ----
        for (int idx = tid; idx < G * D2; idx += NTH) {
            int i = idx / D2, d = idx - i * D2;
            int b = (item0 + i) & 255;
            sm[OFF_CC + i * CCS + d] = passEnc[((size_t)te * NB + b) * D2 + d];
        }
        __syncthreads();

        // ---- phase 1: e = WPu@p + WPv@h + biases ----
        if (p1_act) {
            ull acc = pack2(b_ph1, 0.0f);
            const ull* pp = reinterpret_cast<const ull*>(sm + OFF_CC + i1 * CCS);
#pragma unroll 5
            for (int k = 0; k < D2 / 2; k++) fma2(acc, wpu_row[k], pp[k]);
            float accs = 0.0f;
            const float* hh = sm + OFF_H + i1 * HP;
#pragma unroll 15
            for (int k = 0; k < H; k++) accs = fmaf(wpv_row[k], hh[k], accs);
            sm[OFF_E + i1 * HP + j1] = hsum2(acc) + accs;
        }
        __syncthreads();

        // ---- phase 2: scores s[i][q] = sum_j tanh(qp+e) * v ----
        {
            const float* ee = sm + OFF_E + i2 * HP;
            const float* vv = sm + OFF_V + i2 * HP;
            float acc = 0.0f;
            for (int j = j2lo; j < j2hi; j++) {
                float xx = qp_row[j] + ee[j];
                acc = fmaf(tanhfast(xx), vv[j], acc);
            }
            sm[OFF_PART + half * (G * LQ) + i2 * LQ + q2] = acc;
        }
        __syncthreads();

        // ---- phase 3: softmax over q (warp w = item w) ----
        {
            int wid = tid >> 5, lane = tid & 31;
            if (wid < G) {
                float v0 = sm[OFF_PART + wid * LQ + lane]      + sm[OFF_PART + G * LQ + wid * LQ + lane];
                float v1 = sm[OFF_PART + wid * LQ + lane + 32] + sm[OFF_PART + G * LQ + wid * LQ + lane + 32];
                float m = fmaxf(v0, v1);
#pragma unroll
                for (int o = 16; o > 0; o >>= 1) m = fmaxf(m, __shfl_xor_sync(0xffffffffu, m, o));
                float e0 = __expf(v0 - m), e1 = __expf(v1 - m);
                float s = e0 + e1;
#pragma unroll
                for (int o = 16; o > 0; o >>= 1) s += __shfl_xor_sync(0xffffffffu, s, o);
                float inv = __fdividef(1.0f, s);
                sm[OFF_S + wid * LQ + lane]      = e0 * inv;
                sm[OFF_S + wid * LQ + lane + 32] = e1 * inv;
            }
        }
        __syncthreads();

        // ---- phase 4: context c = a @ quesEnc_b -> cc[150..300) ----
        for (int idx = tid; idx < G * D2; idx += NTH) {
            int i = idx / D2, d = idx - i * D2;
            int b = (item0 + i) & 255;
            const float* qe = quesEnc + (size_t)b * D2 + d;
            const float* aa = sm + OFF_S + i * LQ;
            float acc = 0.0f;
#pragma unroll 8
            for (int q = 0; q < LQ; q++) acc = fmaf(aa[q], qe[(size_t)q * NB * D2], acc);
            sm[OFF_CC + i * CCS + D2 + d] = acc;
        }
        __syncthreads();

        // ---- phase 5: x = sigmoid(cc @ Wg.T + b) * cc  (f32x2, 4-item reuse) ----
        if (p5_act) {
            ull a0l = pack2(b_g, 0.0f), a0h = 0ull;
            ull a1l = pack2(b_g, 0.0f), a1h = 0ull;
            ull a2l = pack2(b_g, 0.0f), a2h = 0ull;
            ull a3l = pack2(b_g, 0.0f), a3h = 0ull;
            const ulonglong2* x0 = reinterpret_cast<const ulonglong2*>(sm + OFF_CC);
            const ulonglong2* x1 = reinterpret_cast<const ulonglong2*>(sm + OFF_CC + CCS);
            const ulonglong2* x2 = reinterpret_cast<const ulonglong2*>(sm + OFF_CC + 2 * CCS);
            const ulonglong2* x3 = reinterpret_cast<const ulonglong2*>(sm + OFF_CC + 3 * CCS);
#pragma unroll 5
            for (int k = 0; k < H4 / 4; k++) {
                ulonglong2 w = wg_row[k];
                ulonglong2 v;
                v = x0[k]; fma2(a0l, w.x, v.x); fma2(a0h, w.y, v.y);
                v = x1[k]; fma2(a1l, w.x, v.x); fma2(a1h, w.y, v.y);
                v = x2[k]; fma2(a2l, w.x, v.x); fma2(a2h, w.y, v.y);
                v = x3[k]; fma2(a3l, w.x, v.x); fma2(a3h, w.y, v.y);
            }
            int j = tid;
            sm[OFF_X + 0 * CCS + j] = sigf(hsum2(a0l) + hsum2(a0h)) * sm[OFF_CC + 0 * CCS + j];
            sm[OFF_X + 1 * CCS + j] = sigf(hsum2(a1l) + hsum2(a1h)) * sm[OFF_CC + 1 * CCS + j];
            sm[OFF_X + 2 * CCS + j] = sigf(hsum2(a2l) + hsum2(a2h)) * sm[OFF_CC + 2 * CCS + j];
            sm[OFF_X + 3 * CCS + j] = sigf(hsum2(a3l) + hsum2(a3h)) * sm[OFF_CC + 3 * CCS + j];
        }
        __syncthreads();

        // ---- phase 6: GRU GEMVs (gi = x@Wih.T in threads [0,225),
        //                          gh = h@Whh.T in threads [256,481)) ----
        if (p6a) {
            ull a0l = pack2(b_ih, 0.0f), a0h = 0ull;
            ull a1l = pack2(b_ih, 0.0f), a1h = 0ull;
            ull a2l = pack2(b_ih, 0.0f), a2h = 0ull;
            ull a3l = pack2(b_ih, 0.0f), a3h = 0ull;
            const ulonglong2* x0 = reinterpret_cast<const ulonglong2*>(sm + OFF_X);
            const ulonglong2* x1 = reinterpret_cast<const ulonglong2*>(sm + OFF_X + CCS);
            const ulonglong2* x2 = reinterpret_cast<const ulonglong2*>(sm + OFF_X + 2 * CCS);
            const ulonglong2* x3 = reinterpret_cast<const ulonglong2*>(sm + OFF_X + 3 * CCS);
#pragma unroll 5
            for (int k = 0; k < H4 / 4; k++) {
                ulonglong2 w = wih_row[k];
                ulonglong2 v;
                v = x0[k]; fma2(a0l, w.x, v.x); fma2(a0h, w.y, v.y);
                v = x1[k]; fma2(a1l, w.x, v.x); fma2(a1h, w.y, v.y);
                v = x2[k]; fma2(a2l, w.x, v.x); fma2(a2h, w.y, v.y);
                v = x3[k]; fma2(a3l, w.x, v.x); fma2(a3h, w.y, v.y);
            }
            int j = tid;
            sm[OFF_GI + 0 * GIS + j] = hsum2(a0l) + hsum2(a0h);
            sm[OFF_GI + 1 * GIS + j] = hsum2(a1l) + hsum2(a1h);
            sm[OFF_GI + 2 * GIS + j] = hsum2(a2l) + hsum2(a2h);
            sm[OFF_GI + 3 * GIS + j] = hsum2(a3l) + hsum2(a3h);
        } else if (p6b) {
            float a0 = b_hh, a1 = b_hh, a2 = b_hh, a3 = b_hh;
#pragma unroll 15
            for (int k = 0; k < H; k++) {
                float w = whh_row[k];
                a0 = fmaf(w, sm[OFF_H + 0 * HP + k], a0);
                a1 = fmaf(w, sm[OFF_H + 1 * HP + k], a1);
                a2 = fmaf(w, sm[OFF_H + 2 * HP + k], a2);
                a3 = fmaf(w, sm[OFF_H + 3 * HP + k], a3);
            }
            sm[OFF_GH + 0 * GIS + jw] = a0;
            sm[OFF_GH + 1 * GIS + jw] = a1;
            sm[OFF_GH + 2 * GIS + jw] = a2;
            sm[OFF_GH + 3 * GIS + jw] = a3;
        }
        __syncthreads();

        // ---- phase 7: GRU combine, update h, write output ----
        if (tid < G * H) {
            int i = tid & 3, j = tid >> 2;
            float gr = sm[OFF_GI + i * GIS + j]         + sm[OFF_GH + i * GIS + j];
            float gz = sm[OFF_GI + i * GIS + H + j]     + sm[OFF_GH + i * GIS + H + j];
            float gin = sm[OFF_GI + i * GIS + 2 * H + j];
            float ghn = sm[OFF_GH + i * GIS + 2 * H + j];
            float r = sigf(gr);
            float z = sigf(gz);
            float n = tanhfast(gin + r * ghn);
            float hprev = sm[OFF_H + i * HP + j];
            float hn = (1.0f - z) * n + z * hprev;
            sm[OFF_H + i * HP + j] = hn;
            int b = (item0 + i) & 255;
            out[((size_t)t * NB + b) * D2 + dir * H + j] = hn;
        }
        __syncthreads();
    }
}

extern "C" void kernel_launch(void* const* d_in, const int* in_sizes, int n_in,
                              void* d_out, int out_size) {
    const float* quesEnc = (const float*)d_in[0];
    const float* passEnc = (const float*)d_in[1];
    const float* WQu_w   = (const float*)d_in[2];
    const float* WQu_b   = (const float*)d_in[3];
    const float* WPu_w   = (const float*)d_in[4];
    const float* WPu_b   = (const float*)d_in[5];
    const float* WPv_w   = (const float*)d_in[6];
    const float* WPv_b   = (const float*)d_in[7];
    const float* Wg_w    = (const float*)d_in[8];
    const float* Wg_b    = (const float*)d_in[9];
    const float* Vt      = (const float*)d_in[10];
    const float* Wih_f   = (const float*)d_in[11];
    const float* Whh_f   = (const float*)d_in[12];
    const float* bih_f   = (const float*)d_in[13];
    const float* bhh_f   = (const float*)d_in[14];
    const float* Wih_r   = (const float*)d_in[15];
    const float* Whh_r   = (const float*)d_in[16];
    const float* bih_r   = (const float*)d_in[17];
    const float* bhh_r   = (const float*)d_in[18];
    const float* h0f     = (const float*)d_in[19];
    const float* h0r     = (const float*)d_in[20];
    float* out = (float*)d_out;

    cudaFuncSetAttribute(persist_kernel,
                         cudaFuncAttributeMaxDynamicSharedMemorySize, SMEM_BYTES);

    qproj_kernel<<<(LQ * NB * H + 255) / 256, 256>>>(quesEnc, WQu_w, WQu_b);
    persist_kernel<<<NBLK, NTH, SMEM_BYTES>>>(quesEnc, passEnc,
                                              WPu_w, WPu_b, WPv_w, WPv_b,
                                              Wg_w, Wg_b, Vt,
                                              Wih_f, Whh_f, bih_f, bhh_f,
                                              Wih_r, Whh_r, bih_r, bhh_r,
                                              h0f, h0r, out);
}

// round 7
// speedup vs baseline: 2.5426x; 1.7432x over previous
#include <cuda_runtime.h>

typedef unsigned long long ull;

// Problem constants
constexpr int H   = 75;
constexpr int H3  = 225;
constexpr int H4  = 300;
constexpr int D2  = 150;
constexpr int NB  = 256;
constexpr int LQ  = 64;
constexpr int LP  = 500;

constexpr int G    = 4;               // (batch,dir) items per block
constexpr int NTH  = 512;
constexpr int NBLK = (2 * NB) / G;    // 128 blocks

// Shared-memory layout (float offsets)
constexpr int HP   = 76;              // row stride for h/v/e (pad [75] = 0)
constexpr int CCS  = 308;             // row stride for cc/x
constexpr int GIS  = 227;             // row stride for gi/gh

constexpr int OFF_QP   = 0;                      // [G][LQ][H]        19200
constexpr int OFF_WHHT = OFF_QP + G * LQ * H;    // [19][225]f4       17100
constexpr int OFF_WPVT = OFF_WHHT + 19 * H3 * 4; // [19][75]f4         5700
constexpr int OFF_WPUT = OFF_WPVT + 19 * H * 4;  // [38][75]f4        11400
constexpr int OFF_H    = OFF_WPUT + 38 * H * 4;  // [G][HP]
constexpr int OFF_V    = OFF_H + G * HP;
constexpr int OFF_E    = OFF_V + G * HP;
constexpr int OFF_S    = OFF_E + G * HP;         // [G][LQ]
constexpr int OFF_CC   = OFF_S + G * LQ;         // [G][CCS]  (GI overlays after ph5)
constexpr int OFF_X    = OFF_CC + G * CCS;       // [G][CCS]  (attention partials overlay ph2-3)
constexpr int OFF_GH   = OFF_X + G * CCS;        // [G][GIS]
constexpr int SMEM_FLOATS = OFF_GH + G * GIS;    // 57940 floats
constexpr int SMEM_BYTES  = SMEM_FLOATS * 4;     // 231760 B

static_assert(OFF_H % 4 == 0 && OFF_CC % 4 == 0 && OFF_X % 4 == 0, "16B align");
static_assert(OFF_WHHT % 4 == 0 && OFF_WPVT % 4 == 0 && OFF_WPUT % 4 == 0, "16B align");
static_assert(SMEM_BYTES <= 232448, "smem over limit");

// Device scratch (static allocation: allowed)
__device__ float g_Qproj[LQ * NB * H];        // quesEnc @ WQu.T + b (step-invariant)
__device__ float g_Wg4[75 * H4 * 4];          // Wg  transposed-interleaved [kb][j][4]
__device__ float g_Wih4[2][75 * H3 * 4];      // Wih transposed-interleaved per dir

// ---------- math helpers ----------
__device__ __forceinline__ float sigf(float x) {
    return __fdividef(1.0f, 1.0f + __expf(-x));
}
__device__ __forceinline__ float tanhfast(float x) {
    return 1.0f - __fdividef(2.0f, __expf(2.0f * x) + 1.0f);
}
__device__ __forceinline__ ull pack2(float x, float y) {
    ull r; asm("mov.b64 %0, {%1, %2};" : "=l"(r) : "f"(x), "f"(y)); return r;
}
__device__ __forceinline__ void fma2(ull& d, ull a, ull b) {
    asm("fma.rn.f32x2 %0, %1, %2, %0;" : "+l"(d) : "l"(a), "l"(b));
}
__device__ __forceinline__ float hsum2(ull a) {
    float x, y; asm("mov.b64 {%0, %1}, %2;" : "=f"(x), "=f"(y) : "l"(a));
    return x + y;
}

// ---------- Qproj precompute ----------
__global__ void qproj_kernel(const float* __restrict__ X,
                             const float* __restrict__ W,
                             const float* __restrict__ bias) {
    int o = blockIdx.x * blockDim.x + threadIdx.x;
    if (o >= LQ * NB * H) return;
    int m = o / H;
    int j = o - m * H;
    const float2* xr = reinterpret_cast<const float2*>(X + (size_t)m * D2);
    const float2* wr = reinterpret_cast<const float2*>(W + (size_t)j * D2);
    float acc = bias[j];
#pragma unroll
    for (int k = 0; k < D2 / 2; k++) {
        float2 x = xr[k], w = wr[k];
        acc = fmaf(x.x, w.x, acc);
        acc = fmaf(x.y, w.y, acc);
    }
    g_Qproj[o] = acc;
}

// ---------- weight transpose: W4[(kb*R + j)*4 + c] = W[j*H4 + kb*4 + c] ----------
__global__ void prep_kernel(const float* __restrict__ Wg,
                            const float* __restrict__ Wf,
                            const float* __restrict__ Wr) {
    int o = blockIdx.x * blockDim.x + threadIdx.x;
    if (o < 90000) {                       // Wg: R=300, 75 kb
        int kb = o / 1200, r = o % 1200, j = r >> 2, c = r & 3;
        g_Wg4[o] = Wg[j * H4 + kb * 4 + c];
    } else if (o < 90000 + 67500) {        // Wih_f: R=225, 75 kb
        int o2 = o - 90000;
        int kb = o2 / 900, r = o2 % 900, j = r >> 2, c = r & 3;
        g_Wih4[0][o2] = Wf[j * H4 + kb * 4 + c];
    } else if (o < 90000 + 135000) {       // Wih_r
        int o2 = o - 157500;
        int kb = o2 / 900, r = o2 % 900, j = r >> 2, c = r & 3;
        g_Wih4[1][o2] = Wr[j * H4 + kb * 4 + c];
    }
}

// ---------- persistent kernel ----------
__global__ __launch_bounds__(NTH, 1)
void persist_kernel(const float* __restrict__ quesEnc,
                    const float* __restrict__ passEnc,
                    const float* __restrict__ WPu_w, const float* __restrict__ WPu_b,
                    const float* __restrict__ WPv_w, const float* __restrict__ WPv_b,
                    const float* __restrict__ Wg_b,
                    const float* __restrict__ Vt,
                    const float* __restrict__ Whh_f,
                    const float* __restrict__ bih_f, const float* __restrict__ bhh_f,
                    const float* __restrict__ Whh_r,
                    const float* __restrict__ bih_r, const float* __restrict__ bhh_r,
                    const float* __restrict__ h0f,   const float* __restrict__ h0r,
                    float* __restrict__ out) {
    extern __shared__ float sm[];
    const int tid   = threadIdx.x;
    const int item0 = blockIdx.x * G;
    const int dir   = item0 >> 8;

    // ---- one-time smem fills (transposed, zero-padded) ----
    {
        const float* Whh = dir ? Whh_r : Whh_f;
        for (int idx = tid; idx < 19 * H3 * 4; idx += NTH) {   // WhhT[kb][rr][c]
            int kb = idx / 900, r = idx % 900, rr = r >> 2, c = r & 3;
            int k = kb * 4 + c;
            sm[OFF_WHHT + idx] = (k < H) ? Whh[rr * H + k] : 0.0f;
        }
        for (int idx = tid; idx < 19 * H * 4; idx += NTH) {    // WPvT[kb][j][c]
            int kb = idx / 300, r = idx % 300, j = r >> 2, c = r & 3;
            int k = kb * 4 + c;
            sm[OFF_WPVT + idx] = (k < H) ? WPv_w[j * H + k] : 0.0f;
        }
        for (int idx = tid; idx < 38 * H * 4; idx += NTH) {    // WPuT[kb][j][c]
            int kb = idx / 300, r = idx % 300, j = r >> 2, c = r & 3;
            int k = kb * 4 + c;
            sm[OFF_WPUT + idx] = (k < D2) ? WPu_w[j * D2 + k] : 0.0f;
        }
        const float* h0 = dir ? h0r : h0f;
        for (int idx = tid; idx < G * HP; idx += NTH) {        // h, v with zero pad
            int i = idx / HP, j = idx % HP;
            int b = (item0 + i) & 255;
            sm[OFF_H + idx] = (j < H) ? h0[b * H + j] : 0.0f;
            sm[OFF_V + idx] = (j < H) ? Vt[b * H + j] : 0.0f;
        }
        for (int idx = tid; idx < 2 * G * CCS; idx += NTH)     // zero CC + X (NaN guard)
            sm[OFF_CC + idx] = 0.0f;
        for (int idx = tid; idx < G * LQ * H; idx += NTH) {    // Qproj slice
            int i = idx / (LQ * H);
            int r = idx - i * (LQ * H);
            int q = r / H, j = r - q * H;
            int b = (item0 + i) & 255;
            sm[OFF_QP + idx] = g_Qproj[((size_t)q * NB + b) * H + j];
        }
    }

    // ---- hoisted per-thread constants ----
    const int i1 = tid / H, j1 = tid % H;                      // ph1 / ph5 / ph7 mapping
    const bool p1_act = (tid < G * H);
    const float b_ph1 = p1_act ? (WPu_b[j1] + WPv_b[j1]) : 0.0f;

    const int half = tid & 1, pair = tid >> 1;                 // ph2
    const int i2 = pair >> 6, q2 = pair & 63;
    const int j2lo = half ? 38 : 0;
    const int j2hi = half ? H  : 38;
    const float* qp_row = sm + OFF_QP + i2 * (LQ * H) + q2 * H;

    const float b_g  = (tid < H4) ? Wg_b[tid] : 0.0f;          // ph5 (tid<300)
    const float b_ih = (tid < H3) ? (dir ? bih_r : bih_f)[tid] : 0.0f;  // ph6
    const float* bhh_d = dir ? bhh_r : bhh_f;

    const ulonglong2* wg_base = reinterpret_cast<const ulonglong2*>(g_Wg4) + tid;
    const ulonglong2* wi_base = reinterpret_cast<const ulonglong2*>(g_Wih4[dir]) + tid;

    const ull* x0c = reinterpret_cast<const ull*>(sm + OFF_CC);
    const ull* x1c = reinterpret_cast<const ull*>(sm + OFF_CC + CCS);
    const ull* x2c = reinterpret_cast<const ull*>(sm + OFF_CC + 2 * CCS);
    const ull* x3c = reinterpret_cast<const ull*>(sm + OFF_CC + 3 * CCS);
    const ull* x0x = reinterpret_cast<const ull*>(sm + OFF_X);
    const ull* x1x = reinterpret_cast<const ull*>(sm + OFF_X + CCS);
    const ull* x2x = reinterpret_cast<const ull*>(sm + OFF_X + 2 * CCS);
    const ull* x3x = reinterpret_cast<const ull*>(sm + OFF_X + 3 * CCS);
    const ull* hh0 = reinterpret_cast<const ull*>(sm + OFF_H);
    const ull* hh1 = reinterpret_cast<const ull*>(sm + OFF_H + HP);
    const ull* hh2 = reinterpret_cast<const ull*>(sm + OFF_H + 2 * HP);
    const ull* hh3 = reinterpret_cast<const ull*>(sm + OFF_H + 3 * HP);

    __syncthreads();

    // ================= main 500-step loop =================
    for (int t = 0; t < LP; t++) {
        const int te = dir ? (LP - 1 - t) : t;

        // ---- phase 0: load p -> cc[0..150) (float2 vectorized) ----
        if (tid < G * 75) {
            int i = tid / 75, d2 = tid % 75;
            int b = (item0 + i) & 255;
            float2 v = reinterpret_cast<const float2*>(passEnc)[((size_t)te * NB + b) * 75 + d2];
            reinterpret_cast<float2*>(sm + OFF_CC + i * CCS)[d2] = v;
        }
        __syncthreads();

        // ---- phase 1: e = WPu@p + WPv@h (coalesced smem weights)
        //      + concurrently gh = h@Whh.T + bhh on threads 300..511 ----
        if (p1_act) {
            ull aA = pack2(b_ph1, 0.0f), aB = 0ull;
            const ulonglong2* wpu = reinterpret_cast<const ulonglong2*>(sm + OFF_WPUT);
            const ulonglong2* wpv = reinterpret_cast<const ulonglong2*>(sm + OFF_WPVT);
            const ull* pp = (i1 == 0) ? x0c : (i1 == 1) ? x1c : (i1 == 2) ? x2c : x3c;
            const ull* hh = (i1 == 0) ? hh0 : (i1 == 1) ? hh1 : (i1 == 2) ? hh2 : hh3;
#pragma unroll 19
            for (int kb = 0; kb < 38; kb++) {
                ulonglong2 w = wpu[kb * H + j1];
                fma2(aA, w.x, pp[2 * kb]); fma2(aB, w.y, pp[2 * kb + 1]);
            }
#pragma unroll 19
            for (int kb = 0; kb < 19; kb++) {
                ulonglong2 w = wpv[kb * H + j1];
                fma2(aA, w.x, hh[2 * kb]); fma2(aB, w.y, hh[2 * kb + 1]);
            }
            sm[OFF_E + i1 * HP + j1] = hsum2(aA) + hsum2(aB);
        } else {
            const ulonglong2* whh = reinterpret_cast<const ulonglong2*>(sm + OFF_WHHT);
            for (int rr = tid - 300; rr < H3; rr += 212) {
                ull a0A = 0, a0B = 0, a1A = 0, a1B = 0;
                ull a2A = 0, a2B = 0, a3A = 0, a3B = 0;
#pragma unroll 19
                for (int kb = 0; kb < 19; kb++) {
                    ulonglong2 w = whh[kb * H3 + rr];
                    fma2(a0A, w.x, hh0[2 * kb]); fma2(a0B, w.y, hh0[2 * kb + 1]);
                    fma2(a1A, w.x, hh1[2 * kb]); fma2(a1B, w.y, hh1[2 * kb + 1]);
                    fma2(a2A, w.x, hh2[2 * kb]); fma2(a2B, w.y, hh2[2 * kb + 1]);
                    fma2(a3A, w.x, hh3[2 * kb]); fma2(a3B, w.y, hh3[2 * kb + 1]);
                }
                float bb = bhh_d[rr];
                sm[OFF_GH + 0 * GIS + rr] = hsum2(a0A) + hsum2(a0B) + bb;
                sm[OFF_GH + 1 * GIS + rr] = hsum2(a1A) + hsum2(a1B) + bb;
                sm[OFF_GH + 2 * GIS + rr] = hsum2(a2A) + hsum2(a2B) + bb;
                sm[OFF_GH + 3 * GIS + rr] = hsum2(a3A) + hsum2(a3B) + bb;
            }
        }
        __syncthreads();

        // ---- phase 2: attention scores (partials -> X region) ----
        {
            const float* ee = sm + OFF_E + i2 * HP;
            const float* vv = sm + OFF_V + i2 * HP;
            float acc = 0.0f;
            for (int j = j2lo; j < j2hi; j++) {
                float xx = qp_row[j] + ee[j];
                acc = fmaf(tanhfast(xx), vv[j], acc);
            }
            sm[OFF_X + half * (G * LQ) + i2 * LQ + q2] = acc;
        }
        __syncthreads();

        // ---- phase 3: softmax over q (warp w = item w) ----
        {
            int wid = tid >> 5, lane = tid & 31;
            if (wid < G) {
                float v0 = sm[OFF_X + wid * LQ + lane]      + sm[OFF_X + G * LQ + wid * LQ + lane];
                float v1 = sm[OFF_X + wid * LQ + lane + 32] + sm[OFF_X + G * LQ + wid * LQ + lane + 32];
                float m = fmaxf(v0, v1);
#pragma unroll
                for (int o = 16; o > 0; o >>= 1) m = fmaxf(m, __shfl_xor_sync(0xffffffffu, m, o));
                float e0 = __expf(v0 - m), e1 = __expf(v1 - m);
                float s = e0 + e1;
#pragma unroll
                for (int o = 16; o > 0; o >>= 1) s += __shfl_xor_sync(0xffffffffu, s, o);
                float inv = __fdividef(1.0f, s);
                sm[OFF_S + wid * LQ + lane]      = e0 * inv;
                sm[OFF_S + wid * LQ + lane + 32] = e1 * inv;
            }
        }
        __syncthreads();

        // ---- phase 4: context c = a @ quesEnc_b -> cc[150..300) ----
        for (int idx = tid; idx < G * D2; idx += NTH) {
            int i = idx / D2, d = idx - i * D2;
            int b = (item0 + i) & 255;
            const float* qe = quesEnc + (size_t)b * D2 + d;
            const float* aa = sm + OFF_S + i * LQ;
            float acc = 0.0f;
#pragma unroll 16
            for (int q = 0; q < LQ; q++) acc = fmaf(aa[q], qe[(size_t)q * NB * D2], acc);
            sm[OFF_CC + i * CCS + D2 + d] = acc;
        }
        __syncthreads();

        // ---- phase 5: x = sigmoid(cc @ Wg.T + b) * cc  (coalesced Wg4 stream) ----
        if (tid < H4) {
            ull a0A = 0, a0B = 0, a1A = 0, a1B = 0;
            ull a2A = 0, a2B = 0, a3A = 0, a3B = 0;
#pragma unroll 15
            for (int kb = 0; kb < 75; kb++) {
                ulonglong2 w = wg_base[kb * H4];
                fma2(a0A, w.x, x0c[2 * kb]); fma2(a0B, w.y, x0c[2 * kb + 1]);
                fma2(a1A, w.x, x1c[2 * kb]); fma2(a1B, w.y, x1c[2 * kb + 1]);
                fma2(a2A, w.x, x2c[2 * kb]); fma2(a2B, w.y, x2c[2 * kb + 1]);
                fma2(a3A, w.x, x3c[2 * kb]); fma2(a3B, w.y, x3c[2 * kb + 1]);
            }
            int j = tid;
            sm[OFF_X + 0 * CCS + j] = sigf(hsum2(a0A) + hsum2(a0B) + b_g) * sm[OFF_CC + 0 * CCS + j];
            sm[OFF_X + 1 * CCS + j] = sigf(hsum2(a1A) + hsum2(a1B) + b_g) * sm[OFF_CC + 1 * CCS + j];
            sm[OFF_X + 2 * CCS + j] = sigf(hsum2(a2A) + hsum2(a2B) + b_g) * sm[OFF_CC + 2 * CCS + j];
            sm[OFF_X + 3 * CCS + j] = sigf(hsum2(a3A) + hsum2(a3B) + b_g) * sm[OFF_CC + 3 * CCS + j];
        }
        __syncthreads();

        // ---- phase 6: gi = x @ Wih.T + bih (coalesced Wih4 stream; GI overlays CC) ----
        if (tid < H3) {
            ull a0A = 0, a0B = 0, a1A = 0, a1B = 0;
            ull a2A = 0, a2B = 0, a3A = 0, a3B = 0;
#pragma unroll 15
            for (int kb = 0; kb < 75; kb++) {
                ulonglong2 w = wi_base[kb * H3];
                fma2(a0A, w.x, x0x[2 * kb]); fma2(a0B, w.y, x0x[2 * kb + 1]);
                fma2(a1A, w.x, x1x[2 * kb]); fma2(a1B, w.y, x1x[2 * kb + 1]);
                fma2(a2A, w.x, x2x[2 * kb]); fma2(a2B, w.y, x2x[2 * kb + 1]);
                fma2(a3A, w.x, x3x[2 * kb]); fma2(a3B, w.y, x3x[2 * kb + 1]);
            }
            sm[OFF_CC + 0 * GIS + tid] = hsum2(a0A) + hsum2(a0B) + b_ih;
            sm[OFF_CC + 1 * GIS + tid] = hsum2(a1A) + hsum2(a1B) + b_ih;
            sm[OFF_CC + 2 * GIS + tid] = hsum2(a2A) + hsum2(a2B) + b_ih;
            sm[OFF_CC + 3 * GIS + tid] = hsum2(a3A) + hsum2(a3B) + b_ih;
        }
        __syncthreads();

        // ---- phase 7: GRU combine, update h, write output ----
        if (tid < G * H) {
            int i = i1, j = j1;
            float gr  = sm[OFF_CC + i * GIS + j]         + sm[OFF_GH + i * GIS + j];
            float gz  = sm[OFF_CC + i * GIS + H + j]     + sm[OFF_GH + i * GIS + H + j];
            float gin = sm[OFF_CC + i * GIS + 2 * H + j];
            float ghn = sm[OFF_GH + i * GIS + 2 * H + j];
            float r = sigf(gr);
            float z = sigf(gz);
            float n = tanhfast(gin + r * ghn);
            float hn = (1.0f - z) * n + z * sm[OFF_H + i * HP + j];
            sm[OFF_H + i * HP + j] = hn;
            int b = (item0 + i) & 255;
            out[((size_t)t * NB + b) * D2 + dir * H + j] = hn;
        }
        __syncthreads();
    }
}

extern "C" void kernel_launch(void* const* d_in, const int* in_sizes, int n_in,
                              void* d_out, int out_size) {
    const float* quesEnc = (const float*)d_in[0];
    const float* passEnc = (const float*)d_in[1];
    const float* WQu_w   = (const float*)d_in[2];
    const float* WQu_b   = (const float*)d_in[3];
    const float* WPu_w   = (const float*)d_in[4];
    const float* WPu_b   = (const float*)d_in[5];
    const float* WPv_w   = (const float*)d_in[6];
    const float* WPv_b   = (const float*)d_in[7];
    const float* Wg_w    = (const float*)d_in[8];
    const float* Wg_b    = (const float*)d_in[9];
    const float* Vt      = (const float*)d_in[10];
    const float* Wih_f   = (const float*)d_in[11];
    const float* Whh_f   = (const float*)d_in[12];
    const float* bih_f   = (const float*)d_in[13];
    const float* bhh_f   = (const float*)d_in[14];
    const float* Wih_r   = (const float*)d_in[15];
    const float* Whh_r   = (const float*)d_in[16];
    const float* bih_r   = (const float*)d_in[17];
    const float* bhh_r   = (const float*)d_in[18];
    const float* h0f     = (const float*)d_in[19];
    const float* h0r     = (const float*)d_in[20];
    float* out = (float*)d_out;

    cudaFuncSetAttribute(persist_kernel,
                         cudaFuncAttributeMaxDynamicSharedMemorySize, SMEM_BYTES);

    qproj_kernel<<<(LQ * NB * H + 255) / 256, 256>>>(quesEnc, WQu_w, WQu_b);
    prep_kernel<<<(225000 + 255) / 256, 256>>>(Wg_w, Wih_f, Wih_r);
    persist_kernel<<<NBLK, NTH, SMEM_BYTES>>>(quesEnc, passEnc,
                                              WPu_w, WPu_b, WPv_w, WPv_b,
                                              Wg_b, Vt,
                                              Whh_f, bih_f, bhh_f,
                                              Whh_r, bih_r, bhh_r,
                                              h0f, h0r, out);
}

// round 9
// speedup vs baseline: 2.8883x; 1.1360x over previous
#include <cuda_runtime.h>
#include <cuda_fp16.h>

typedef unsigned long long ull;

// Problem constants
constexpr int H   = 75;
constexpr int H3  = 225;
constexpr int H4  = 300;
constexpr int D2  = 150;
constexpr int NB  = 256;
constexpr int LQ  = 64;
constexpr int LP  = 500;

constexpr int G    = 4;
constexpr int NTH  = 512;
constexpr int NBLK = (2 * NB) / G;    // 128 blocks

constexpr int KB8 = 38;               // ceil(300/8) fp16-packed k-blocks

// Shared-memory layout (float-slot offsets)
constexpr int HP   = 76;
constexpr int CCS  = 308;
constexpr int GIS  = 227;

constexpr int OFF_QPH  = 0;                          // 19200 halves = 9600 slots
constexpr int OFF_WHHT = 9600;                       // [19][225][4] = 17100
constexpr int OFF_WPVT = OFF_WHHT + 19 * H3 * 4;     // [19][75][4]  = 5700
constexpr int OFF_WPUT = OFF_WPVT + 19 * H * 4;      // [38][75][4]  = 11400
constexpr int OFF_H    = OFF_WPUT + 38 * H * 4;      // [G][HP]
constexpr int OFF_V    = OFF_H + G * HP;
constexpr int OFF_E    = OFF_V + G * HP;
constexpr int OFF_S    = OFF_E + G * HP;             // [G][LQ]
constexpr int OFF_PART = OFF_S + G * LQ;             // [2][G][LQ] = 512
constexpr int OFF_CC   = OFF_PART + 2 * G * LQ;      // [G][CCS]
constexpr int OFF_X    = OFF_CC + G * CCS;           // [G][CCS]
constexpr int OFF_GI   = OFF_X + G * CCS;            // [G][GIS]
constexpr int OFF_GH   = OFF_GI + G * GIS;           // [G][GIS]
constexpr int SMEM_FLOATS = OFF_GH + G * GIS;        // 49760 floats
constexpr int SMEM_BYTES  = SMEM_FLOATS * 4;         // 199040 B

static_assert(OFF_WHHT % 4 == 0 && OFF_WPVT % 4 == 0 && OFF_WPUT % 4 == 0, "align");
static_assert(OFF_H % 4 == 0 && OFF_CC % 4 == 0 && OFF_X % 4 == 0, "align");
static_assert(SMEM_BYTES <= 232448, "smem over limit");

// Device scratch (static allocation: allowed).
// __align__(16) makes the uint4 casts contractually safe.
__device__ __half g_QprojH[LQ * NB * H];                      // quesEnc @ WQu.T + b, fp16
__device__ float  g_WQuT[D2 * H];                             // WQu transposed [k][j]
__device__ __align__(16) __half g_Wg4h[KB8 * H4 * 8];         // Wg fp16 [kb][j][8]
__device__ __align__(16) __half g_Wih4h[2][KB8 * H3 * 8];     // Wih fp16 per dir

// ---------- math helpers ----------
__device__ __forceinline__ float tanha(float x) {
    float r; asm("tanh.approx.f32 %0, %1;" : "=f"(r) : "f"(x)); return r;
}
__device__ __forceinline__ float siga(float x) {
    return fmaf(tanha(0.5f * x), 0.5f, 0.5f);
}
__device__ __forceinline__ ull pack2(float x, float y) {
    ull r; asm("mov.b64 %0, {%1, %2};" : "=l"(r) : "f"(x), "f"(y)); return r;
}
__device__ __forceinline__ void fma2(ull& d, ull a, ull b) {
    asm("fma.rn.f32x2 %0, %1, %2, %0;" : "+l"(d) : "l"(a), "l"(b));
}
__device__ __forceinline__ float hsum2(ull a) {
    float x, y; asm("mov.b64 {%0, %1}, %2;" : "=f"(x), "=f"(y) : "l"(a));
    return x + y;
}
__device__ __forceinline__ ull h2f2(unsigned v) {
    float2 f = __half22float2(*reinterpret_cast<const __half2*>(&v));
    return pack2(f.x, f.y);
}

// ---------- prep: weight transposes / fp16 packs ----------
__global__ void prep_kernel(const float* __restrict__ WQu,
                            const float* __restrict__ Wg,
                            const float* __restrict__ Wf,
                            const float* __restrict__ Wr) {
    int o = blockIdx.x * blockDim.x + threadIdx.x;
    if (o < D2 * H) {                                  // WQuT[k][j]
        int k = o / H, j = o - k * H;
        g_WQuT[o] = WQu[j * D2 + k];
    } else if (o < D2 * H + KB8 * H4 * 8) {            // Wg4h
        int o2 = o - D2 * H;
        int kb = o2 / (H4 * 8), r = o2 % (H4 * 8), j = r >> 3, c = r & 7;
        int k = kb * 8 + c;
        g_Wg4h[o2] = __float2half(k < H4 ? Wg[j * H4 + k] : 0.0f);
    } else if (o < D2 * H + KB8 * H4 * 8 + 2 * KB8 * H3 * 8) {
        int o2 = o - D2 * H - KB8 * H4 * 8;
        int d = o2 / (KB8 * H3 * 8);
        int o3 = o2 - d * (KB8 * H3 * 8);
        int kb = o3 / (H3 * 8), r = o3 % (H3 * 8), j = r >> 3, c = r & 7;
        int k = kb * 8 + c;
        const float* W = d ? Wr : Wf;
        g_Wih4h[d][o3] = __float2half(k < H4 ? W[j * H4 + k] : 0.0f);
    }
}
constexpr int PREP_N = D2 * H + KB8 * H4 * 8 + 2 * KB8 * H3 * 8;

// ---------- Qproj (coalesced via WQuT) ----------
__global__ void qproj_kernel(const float* __restrict__ X,
                             const float* __restrict__ bias) {
    int o = blockIdx.x * blockDim.x + threadIdx.x;
    if (o >= LQ * NB * H) return;
    int m = o / H;
    int j = o - m * H;
    const float* xr = X + (size_t)m * D2;
    float acc = bias[j];
#pragma unroll 15
    for (int k = 0; k < D2; k++) acc = fmaf(xr[k], g_WQuT[k * H + j], acc);
    g_QprojH[o] = __float2half(acc);
}

// ---------- persistent kernel ----------
__global__ __launch_bounds__(NTH, 1)
void persist_kernel(const float* __restrict__ quesEnc,
                    const float* __restrict__ passEnc,
                    const float* __restrict__ WPu_w, const float* __restrict__ WPu_b,
                    const float* __restrict__ WPv_w, const float* __restrict__ WPv_b,
                    const float* __restrict__ Wg_b,
                    const float* __restrict__ Vt,
                    const float* __restrict__ Whh_f,
                    const float* __restrict__ bih_f, const float* __restrict__ bhh_f,
                    const float* __restrict__ Whh_r,
                    const float* __restrict__ bih_r, const float* __restrict__ bhh_r,
                    const float* __restrict__ h0f,   const float* __restrict__ h0r,
                    float* __restrict__ out) {
    extern __shared__ float sm[];
    __half* smh = reinterpret_cast<__half*>(sm + OFF_QPH);
    const int tid   = threadIdx.x;
    const int item0 = blockIdx.x * G;
    const int dir   = item0 >> 8;

    // ---- one-time smem fills ----
    {
        const float* Whh = dir ? Whh_r : Whh_f;
        for (int idx = tid; idx < 19 * H3 * 4; idx += NTH) {
            int kb = idx / 900, r = idx % 900, rr = r >> 2, c = r & 3;
            int k = kb * 4 + c;
            sm[OFF_WHHT + idx] = (k < H) ? Whh[rr * H + k] : 0.0f;
        }
        for (int idx = tid; idx < 19 * H * 4; idx += NTH) {
            int kb = idx / 300, r = idx % 300, j = r >> 2, c = r & 3;
            int k = kb * 4 + c;
            sm[OFF_WPVT + idx] = (k < H) ? WPv_w[j * H + k] : 0.0f;
        }
        for (int idx = tid; idx < 38 * H * 4; idx += NTH) {
            int kb = idx / 300, r = idx % 300, j = r >> 2, c = r & 3;
            int k = kb * 4 + c;
            sm[OFF_WPUT + idx] = (k < D2) ? WPu_w[j * D2 + k] : 0.0f;
        }
        const float* h0 = dir ? h0r : h0f;
        for (int idx = tid; idx < G * HP; idx += NTH) {
            int i = idx / HP, j = idx % HP;
            int b = (item0 + i) & 255;
            sm[OFF_H + idx] = (j < H) ? h0[b * H + j] : 0.0f;
            sm[OFF_V + idx] = (j < H) ? Vt[b * H + j] : 0.0f;
        }
        for (int idx = tid; idx < 2 * G * CCS; idx += NTH)   // zero CC + X (pads!)
            sm[OFF_CC + idx] = 0.0f;
        for (int idx = tid; idx < G * LQ * H; idx += NTH) {  // Qproj fp16 slice
            int i = idx / (LQ * H);
            int r = idx - i * (LQ * H);
            int q = r / H, j = r - q * H;
            int b = (item0 + i) & 255;
            smh[idx] = g_QprojH[((size_t)q * NB + b) * H + j];
        }
        // p(0)
        int te0 = dir ? (LP - 1) : 0;
        for (int idx = tid; idx < G * D2; idx += NTH) {
            int i = idx / D2, d = idx - i * D2;
            int b = (item0 + i) & 255;
            sm[OFF_CC + i * CCS + d] = passEnc[((size_t)te0 * NB + b) * D2 + d];
        }
    }

    // ---- hoisted per-thread constants ----
    const int i1 = tid / H, j1 = tid % H;
    const bool p1_act = (tid < G * H);
    const float b_ph1 = p1_act ? (WPu_b[j1] + WPv_b[j1]) : 0.0f;

    const int half = tid & 1, pair = tid >> 1;
    const int i2 = pair >> 6, q2 = pair & 63;
    const int j2lo = half ? 38 : 0;
    const int j2hi = half ? H  : 38;
    const __half* qp_row = smh + i2 * (LQ * H) + q2 * H;

    const float b_g  = (tid < H4) ? Wg_b[tid] : 0.0f;
    const float b_ih = (tid < H3) ? (dir ? bih_r : bih_f)[tid] : 0.0f;
    const float* bhh_d = dir ? bhh_r : bhh_f;

    const uint4* wg_base = reinterpret_cast<const uint4*>(g_Wg4h) + tid;
    const uint4* wi_base = reinterpret_cast<const uint4*>(g_Wih4h[dir]) + tid;

    const ull* x0c = reinterpret_cast<const ull*>(sm + OFF_CC);
    const ull* x1c = reinterpret_cast<const ull*>(sm + OFF_CC + CCS);
    const ull* x2c = reinterpret_cast<const ull*>(sm + OFF_CC + 2 * CCS);
    const ull* x3c = reinterpret_cast<const ull*>(sm + OFF_CC + 3 * CCS);
    const ull* x0x = reinterpret_cast<const ull*>(sm + OFF_X);
    const ull* x1x = reinterpret_cast<const ull*>(sm + OFF_X + CCS);
    const ull* x2x = reinterpret_cast<const ull*>(sm + OFF_X + 2 * CCS);
    const ull* x3x = reinterpret_cast<const ull*>(sm + OFF_X + 3 * CCS);
    const ull* hh0 = reinterpret_cast<const ull*>(sm + OFF_H);
    const ull* hh1 = reinterpret_cast<const ull*>(sm + OFF_H + HP);
    const ull* hh2 = reinterpret_cast<const ull*>(sm + OFF_H + 2 * HP);
    const ull* hh3 = reinterpret_cast<const ull*>(sm + OFF_H + 3 * HP);

    __syncthreads();

    // ================= main 500-step loop =================
    for (int t = 0; t < LP; t++) {
        float pf0 = 0.0f, pf1 = 0.0f, pf2 = 0.0f;   // p(t+1) prefetch regs

        // ---- phase 1: e = WPu@p + WPv@h  ||  gh = h@Whh.T + bhh ----
        if (p1_act) {
            ull aA = pack2(b_ph1, 0.0f), aB = 0ull;
            const ulonglong2* wpu = reinterpret_cast<const ulonglong2*>(sm + OFF_WPUT);
            const ulonglong2* wpv = reinterpret_cast<const ulonglong2*>(sm + OFF_WPVT);
            const ull* pp = (i1 == 0) ? x0c : (i1 == 1) ? x1c : (i1 == 2) ? x2c : x3c;
            const ull* hh = (i1 == 0) ? hh0 : (i1 == 1) ? hh1 : (i1 == 2) ? hh2 : hh3;
#pragma unroll 19
            for (int kb = 0; kb < 38; kb++) {
                ulonglong2 w = wpu[kb * H + j1];
                fma2(aA, w.x, pp[2 * kb]); fma2(aB, w.y, pp[2 * kb + 1]);
            }
#pragma unroll 19
            for (int kb = 0; kb < 19; kb++) {
                ulonglong2 w = wpv[kb * H + j1];
                fma2(aA, w.x, hh[2 * kb]); fma2(aB, w.y, hh[2 * kb + 1]);
            }
            sm[OFF_E + i1 * HP + j1] = hsum2(aA) + hsum2(aB);
        } else {
            const ulonglong2* whh = reinterpret_cast<const ulonglong2*>(sm + OFF_WHHT);
            for (int rr = tid - 300; rr < H3; rr += 212) {
                ull a0A = 0, a0B = 0, a1A = 0, a1B = 0;
                ull a2A = 0, a2B = 0, a3A = 0, a3B = 0;
#pragma unroll 19
                for (int kb = 0; kb < 19; kb++) {
                    ulonglong2 w = whh[kb * H3 + rr];
                    fma2(a0A, w.x, hh0[2 * kb]); fma2(a0B, w.y, hh0[2 * kb + 1]);
                    fma2(a1A, w.x, hh1[2 * kb]); fma2(a1B, w.y, hh1[2 * kb + 1]);
                    fma2(a2A, w.x, hh2[2 * kb]); fma2(a2B, w.y, hh2[2 * kb + 1]);
                    fma2(a3A, w.x, hh3[2 * kb]); fma2(a3B, w.y, hh3[2 * kb + 1]);
                }
                float bb = bhh_d[rr];
                sm[OFF_GH + 0 * GIS + rr] = hsum2(a0A) + hsum2(a0B) + bb;
                sm[OFF_GH + 1 * GIS + rr] = hsum2(a1A) + hsum2(a1B) + bb;
                sm[OFF_GH + 2 * GIS + rr] = hsum2(a2A) + hsum2(a2B) + bb;
                sm[OFF_GH + 3 * GIS + rr] = hsum2(a3A) + hsum2(a3B) + bb;
            }
        }
        __syncthreads();

        // ---- phase 2: attention scores (tanh.approx) ----
        {
            const float* ee = sm + OFF_E + i2 * HP;
            const float* vv = sm + OFF_V + i2 * HP;
            float acc = 0.0f;
            for (int j = j2lo; j < j2hi; j++) {
                float xx = __half2float(qp_row[j]) + ee[j];
                acc = fmaf(tanha(xx), vv[j], acc);
            }
            sm[OFF_PART + half * (G * LQ) + i2 * LQ + q2] = acc;
        }
        __syncthreads();

        // ---- phase 3: softmax ----
        {
            int wid = tid >> 5, lane = tid & 31;
            if (wid < G) {
                float v0 = sm[OFF_PART + wid * LQ + lane]      + sm[OFF_PART + G * LQ + wid * LQ + lane];
                float v1 = sm[OFF_PART + wid * LQ + lane + 32] + sm[OFF_PART + G * LQ + wid * LQ + lane + 32];
                float m = fmaxf(v0, v1);
#pragma unroll
                for (int o = 16; o > 0; o >>= 1) m = fmaxf(m, __shfl_xor_sync(0xffffffffu, m, o));
                float e0 = __expf(v0 - m), e1 = __expf(v1 - m);
                float s = e0 + e1;
#pragma unroll
                for (int o = 16; o > 0; o >>= 1) s += __shfl_xor_sync(0xffffffffu, s, o);
                float inv = __fdividef(1.0f, s);
                sm[OFF_S + wid * LQ + lane]      = e0 * inv;
                sm[OFF_S + wid * LQ + lane + 32] = e1 * inv;
            }
        }
        __syncthreads();

        // ---- phase 4: context c -> cc[150..300) ----
        for (int idx = tid; idx < G * D2; idx += NTH) {
            int i = idx / D2, d = idx - i * D2;
            int b = (item0 + i) & 255;
            const float* qe = quesEnc + (size_t)b * D2 + d;
            const float* aa = sm + OFF_S + i * LQ;
            float acc = 0.0f;
#pragma unroll 16
            for (int q = 0; q < LQ; q++) acc = fmaf(aa[q], qe[(size_t)q * NB * D2], acc);
            sm[OFF_CC + i * CCS + D2 + d] = acc;
        }
        __syncthreads();

        // ---- phase 5: x = sigmoid(Wg@cc + b)*cc (fp16 stream) || prefetch p(t+1) ----
        if (tid < H4) {
            ull a0A = 0, a0B = 0, a1A = 0, a1B = 0;
            ull a2A = 0, a2B = 0, a3A = 0, a3B = 0;
#pragma unroll 19
            for (int kb = 0; kb < KB8; kb++) {
                uint4 w = wg_base[kb * H4];
                ull w0 = h2f2(w.x), w1 = h2f2(w.y), w2 = h2f2(w.z), w3 = h2f2(w.w);
                fma2(a0A, w0, x0c[4 * kb]); fma2(a0B, w1, x0c[4 * kb + 1]);
                fma2(a0A, w2, x0c[4 * kb + 2]); fma2(a0B, w3, x0c[4 * kb + 3]);
                fma2(a1A, w0, x1c[4 * kb]); fma2(a1B, w1, x1c[4 * kb + 1]);
                fma2(a1A, w2, x1c[4 * kb + 2]); fma2(a1B, w3, x1c[4 * kb + 3]);
                fma2(a2A, w0, x2c[4 * kb]); fma2(a2B, w1, x2c[4 * kb + 1]);
                fma2(a2A, w2, x2c[4 * kb + 2]); fma2(a2B, w3, x2c[4 * kb + 3]);
                fma2(a3A, w0, x3c[4 * kb]); fma2(a3B, w1, x3c[4 * kb + 1]);
                fma2(a3A, w2, x3c[4 * kb + 2]); fma2(a3B, w3, x3c[4 * kb + 3]);
            }
            int j = tid;
            sm[OFF_X + 0 * CCS + j] = siga(hsum2(a0A) + hsum2(a0B) + b_g) * sm[OFF_CC + 0 * CCS + j];
            sm[OFF_X + 1 * CCS + j] = siga(hsum2(a1A) + hsum2(a1B) + b_g) * sm[OFF_CC + 1 * CCS + j];
            sm[OFF_X + 2 * CCS + j] = siga(hsum2(a2A) + hsum2(a2B) + b_g) * sm[OFF_CC + 2 * CCS + j];
            sm[OFF_X + 3 * CCS + j] = siga(hsum2(a3A) + hsum2(a3B) + b_g) * sm[OFF_CC + 3 * CCS + j];
        } else if (tid >= 308 && tid < 508) {
            int u = tid - 308;
            int tn = (t + 1 < LP) ? t + 1 : t;
            int ten = dir ? (LP - 1 - tn) : tn;
#pragma unroll
            for (int c = 0; c < 3; c++) {
                int e = 3 * u + c;
                int i = e / D2, d = e - i * D2;
                int b = (item0 + i) & 255;
                float v = passEnc[((size_t)ten * NB + b) * D2 + d];
                if (c == 0) pf0 = v; else if (c == 1) pf1 = v; else pf2 = v;
            }
        }
        __syncthreads();

        // ---- phase 6: gi = Wih@x + bih (fp16 stream) ----
        if (tid < H3) {
            ull a0A = 0, a0B = 0, a1A = 0, a1B = 0;
            ull a2A = 0, a2B = 0, a3A = 0, a3B = 0;
#pragma unroll 19
            for (int kb = 0; kb < KB8; kb++) {
                uint4 w = wi_base[kb * H3];
                ull w0 = h2f2(w.x), w1 = h2f2(w.y), w2 = h2f2(w.z), w3 = h2f2(w.w);
                fma2(a0A, w0, x0x[4 * kb]); fma2(a0B, w1, x0x[4 * kb + 1]);
                fma2(a0A, w2, x0x[4 * kb + 2]); fma2(a0B, w3, x0x[4 * kb + 3]);
                fma2(a1A, w0, x1x[4 * kb]); fma2(a1B, w1, x1x[4 * kb + 1]);
                fma2(a1A, w2, x1x[4 * kb + 2]); fma2(a1B, w3, x1x[4 * kb + 3]);
                fma2(a2A, w0, x2x[4 * kb]); fma2(a2B, w1, x2x[4 * kb + 1]);
                fma2(a2A, w2, x2x[4 * kb + 2]); fma2(a2B, w3, x2x[4 * kb + 3]);
                fma2(a3A, w0, x3x[4 * kb]); fma2(a3B, w1, x3x[4 * kb + 1]);
                fma2(a3A, w2, x3x[4 * kb + 2]); fma2(a3B, w3, x3x[4 * kb + 3]);
            }
            sm[OFF_GI + 0 * GIS + tid] = hsum2(a0A) + hsum2(a0B) + b_ih;
            sm[OFF_GI + 1 * GIS + tid] = hsum2(a1A) + hsum2(a1B) + b_ih;
            sm[OFF_GI + 2 * GIS + tid] = hsum2(a2A) + hsum2(a2B) + b_ih;
            sm[OFF_GI + 3 * GIS + tid] = hsum2(a3A) + hsum2(a3B) + b_ih;
        }
        __syncthreads();

        // ---- phase 7: GRU combine + h/out write  ||  store p(t+1) ----
        if (tid < G * H) {
            int i = i1, j = j1;
            float gr  = sm[OFF_GI + i * GIS + j]         + sm[OFF_GH + i * GIS + j];
            float gz  = sm[OFF_GI + i * GIS + H + j]     + sm[OFF_GH + i * GIS + H + j];
            float gin = sm[OFF_GI + i * GIS + 2 * H + j];
            float ghn = sm[OFF_GH + i * GIS + 2 * H + j];
            float r = siga(gr);
            float z = siga(gz);
            float n = tanha(fmaf(r, ghn, gin));
            float hn = (1.0f - z) * n + z * sm[OFF_H + i * HP + j];
            sm[OFF_H + i * HP + j] = hn;
            int b = (item0 + i) & 255;
            out[((size_t)t * NB + b) * D2 + dir * H + j] = hn;
        } else if (tid >= 308 && tid < 508) {
            int u = tid - 308;
#pragma unroll
            for (int c = 0; c < 3; c++) {
                int e = 3 * u + c;
                int i = e / D2, d = e - i * D2;
                float v = (c == 0) ? pf0 : (c == 1) ? pf1 : pf2;
                sm[OFF_CC + i * CCS + d] = v;
            }
        }
        __syncthreads();
    }
}

extern "C" void kernel_launch(void* const* d_in, const int* in_sizes, int n_in,
                              void* d_out, int out_size) {
    const float* quesEnc = (const float*)d_in[0];
    const float* passEnc = (const float*)d_in[1];
    const float* WQu_w   = (const float*)d_in[2];
    const float* WQu_b   = (const float*)d_in[3];
    const float* WPu_w   = (const float*)d_in[4];
    const float* WPu_b   = (const float*)d_in[5];
    const float* WPv_w   = (const float*)d_in[6];
    const float* WPv_b   = (const float*)d_in[7];
    const float* Wg_w    = (const float*)d_in[8];
    const float* Wg_b    = (const float*)d_in[9];
    const float* Vt      = (const float*)d_in[10];
    const float* Wih_f   = (const float*)d_in[11];
    const float* Whh_f   = (const float*)d_in[12];
    const float* bih_f   = (const float*)d_in[13];
    const float* bhh_f   = (const float*)d_in[14];
    const float* Wih_r   = (const float*)d_in[15];
    const float* Whh_r   = (const float*)d_in[16];
    const float* bih_r   = (const float*)d_in[17];
    const float* bhh_r   = (const float*)d_in[18];
    const float* h0f     = (const float*)d_in[19];
    const float* h0r     = (const float*)d_in[20];
    float* out = (float*)d_out;

    cudaFuncSetAttribute(persist_kernel,
                         cudaFuncAttributeMaxDynamicSharedMemorySize, SMEM_BYTES);

    prep_kernel<<<(PREP_N + 255) / 256, 256>>>(WQu_w, Wg_w, Wih_f, Wih_r);
    qproj_kernel<<<(LQ * NB * H + 255) / 256, 256>>>(quesEnc, WQu_b);
    persist_kernel<<<NBLK, NTH, SMEM_BYTES>>>(quesEnc, passEnc,
                                              WPu_w, WPu_b, WPv_w, WPv_b,
                                              Wg_b, Vt,
                                              Whh_f, bih_f, bhh_f,
                                              Whh_r, bih_r, bhh_r,
                                              h0f, h0r, out);
}

// round 10
// speedup vs baseline: 3.3005x; 1.1427x over previous
#include <cuda_runtime.h>
#include <cuda_fp16.h>

typedef unsigned long long ull;

// Problem constants
constexpr int H   = 75;
constexpr int H3  = 225;
constexpr int H4  = 300;
constexpr int D2  = 150;
constexpr int NB  = 256;
constexpr int LQ  = 64;
constexpr int LP  = 500;

constexpr int G    = 4;
constexpr int NTH  = 512;
constexpr int NBLK = (2 * NB) / G;    // 128 blocks

constexpr int KB8 = 38;               // ceil(300/8) fp16-packed k-blocks
constexpr int QPS = 76;               // padded Qproj row stride (halves)

// Shared-memory layout (float-slot offsets)
constexpr int HP   = 76;
constexpr int CCS  = 308;
constexpr int GIS  = 227;

constexpr int OFF_QPH  = 0;                          // [G][LQ][76] halves = 9728 slots
constexpr int OFF_WHHT = 9728;                       // [19][225][4] = 17100
constexpr int OFF_WPVT = OFF_WHHT + 19 * H3 * 4;     // [19][75][4]  = 5700
constexpr int OFF_WPUT = OFF_WPVT + 19 * H * 4;      // [38][75][4]  = 11400
constexpr int OFF_H    = OFF_WPUT + 38 * H * 4;      // [G][HP]
constexpr int OFF_V    = OFF_H + G * HP;
constexpr int OFF_E    = OFF_V + G * HP;
constexpr int OFF_S    = OFF_E + G * HP;             // [G][LQ]
constexpr int OFF_PART = OFF_S + G * LQ;             // [2][G][LQ] = 512
constexpr int OFF_CC   = OFF_PART + 2 * G * LQ;      // [G][CCS]
constexpr int OFF_X    = OFF_CC + G * CCS;           // [G][CCS]
constexpr int OFF_GI   = OFF_X + G * CCS;            // [G][GIS]
constexpr int OFF_GH   = OFF_GI + G * GIS;           // [G][GIS]
constexpr int SMEM_FLOATS = OFF_GH + G * GIS;        // 49888 floats
constexpr int SMEM_BYTES  = SMEM_FLOATS * 4;         // 199552 B

static_assert(OFF_WHHT % 4 == 0 && OFF_WPVT % 4 == 0 && OFF_WPUT % 4 == 0, "align");
static_assert(OFF_H % 4 == 0 && OFF_CC % 4 == 0 && OFF_X % 4 == 0, "align");
static_assert(OFF_E % 2 == 0, "float2 align");
static_assert(SMEM_BYTES <= 232448, "smem over limit");

// Device scratch (static allocation: allowed)
__device__ __half g_QprojH[LQ * NB * H];                      // quesEnc @ WQu.T + b, fp16
__device__ float  g_WQuT[D2 * H];                             // WQu transposed [k][j]
__device__ __align__(16) __half g_Wg4h[KB8 * H4 * 8];         // Wg fp16 [kb][j][8]
__device__ __align__(16) __half g_Wih4h[2][KB8 * H3 * 8];     // Wih fp16 per dir

// ---------- math helpers ----------
__device__ __forceinline__ float tanha(float x) {
    float r; asm("tanh.approx.f32 %0, %1;" : "=f"(r) : "f"(x)); return r;
}
__device__ __forceinline__ float siga(float x) {
    return fmaf(tanha(0.5f * x), 0.5f, 0.5f);
}
__device__ __forceinline__ ull pack2(float x, float y) {
    ull r; asm("mov.b64 %0, {%1, %2};" : "=l"(r) : "f"(x), "f"(y)); return r;
}
__device__ __forceinline__ void fma2(ull& d, ull a, ull b) {
    asm("fma.rn.f32x2 %0, %1, %2, %0;" : "+l"(d) : "l"(a), "l"(b));
}
__device__ __forceinline__ float hsum2(ull a) {
    float x, y; asm("mov.b64 {%0, %1}, %2;" : "=f"(x), "=f"(y) : "l"(a));
    return x + y;
}
__device__ __forceinline__ ull h2f2(unsigned v) {
    float2 f = __half22float2(*reinterpret_cast<const __half2*>(&v));
    return pack2(f.x, f.y);
}

// ---------- prep: weight transposes / fp16 packs ----------
__global__ void prep_kernel(const float* __restrict__ WQu,
                            const float* __restrict__ Wg,
                            const float* __restrict__ Wf,
                            const float* __restrict__ Wr) {
    int o = blockIdx.x * blockDim.x + threadIdx.x;
    if (o < D2 * H) {                                  // WQuT[k][j]
        int k = o / H, j = o - k * H;
        g_WQuT[o] = WQu[j * D2 + k];
    } else if (o < D2 * H + KB8 * H4 * 8) {            // Wg4h
        int o2 = o - D2 * H;
        int kb = o2 / (H4 * 8), r = o2 % (H4 * 8), j = r >> 3, c = r & 7;
        int k = kb * 8 + c;
        g_Wg4h[o2] = __float2half(k < H4 ? Wg[j * H4 + k] : 0.0f);
    } else if (o < D2 * H + KB8 * H4 * 8 + 2 * KB8 * H3 * 8) {
        int o2 = o - D2 * H - KB8 * H4 * 8;
        int d = o2 / (KB8 * H3 * 8);
        int o3 = o2 - d * (KB8 * H3 * 8);
        int kb = o3 / (H3 * 8), r = o3 % (H3 * 8), j = r >> 3, c = r & 7;
        int k = kb * 8 + c;
        const float* W = d ? Wr : Wf;
        g_Wih4h[d][o3] = __float2half(k < H4 ? W[j * H4 + k] : 0.0f);
    }
}
constexpr int PREP_N = D2 * H + KB8 * H4 * 8 + 2 * KB8 * H3 * 8;

// ---------- Qproj (coalesced via WQuT) ----------
__global__ void qproj_kernel(const float* __restrict__ X,
                             const float* __restrict__ bias) {
    int o = blockIdx.x * blockDim.x + threadIdx.x;
    if (o >= LQ * NB * H) return;
    int m = o / H;
    int j = o - m * H;
    const float* xr = X + (size_t)m * D2;
    float acc = bias[j];
#pragma unroll 15
    for (int k = 0; k < D2; k++) acc = fmaf(xr[k], g_WQuT[k * H + j], acc);
    g_QprojH[o] = __float2half(acc);
}

// ---------- persistent kernel ----------
__global__ __launch_bounds__(NTH, 1)
void persist_kernel(const float* __restrict__ quesEnc,
                    const float* __restrict__ passEnc,
                    const float* __restrict__ WPu_w, const float* __restrict__ WPu_b,
                    const float* __restrict__ WPv_w, const float* __restrict__ WPv_b,
                    const float* __restrict__ Wg_b,
                    const float* __restrict__ Vt,
                    const float* __restrict__ Whh_f,
                    const float* __restrict__ bih_f, const float* __restrict__ bhh_f,
                    const float* __restrict__ Whh_r,
                    const float* __restrict__ bih_r, const float* __restrict__ bhh_r,
                    const float* __restrict__ h0f,   const float* __restrict__ h0r,
                    float* __restrict__ out) {
    extern __shared__ float sm[];
    __half* smh = reinterpret_cast<__half*>(sm + OFF_QPH);
    const int tid   = threadIdx.x;
    const int item0 = blockIdx.x * G;
    const int dir   = item0 >> 8;

    // ---- one-time smem fills ----
    {
        const float* Whh = dir ? Whh_r : Whh_f;
        for (int idx = tid; idx < 19 * H3 * 4; idx += NTH) {
            int kb = idx / 900, r = idx % 900, rr = r >> 2, c = r & 3;
            int k = kb * 4 + c;
            sm[OFF_WHHT + idx] = (k < H) ? Whh[rr * H + k] : 0.0f;
        }
        for (int idx = tid; idx < 19 * H * 4; idx += NTH) {
            int kb = idx / 300, r = idx % 300, j = r >> 2, c = r & 3;
            int k = kb * 4 + c;
            sm[OFF_WPVT + idx] = (k < H) ? WPv_w[j * H + k] : 0.0f;
        }
        for (int idx = tid; idx < 38 * H * 4; idx += NTH) {
            int kb = idx / 300, r = idx % 300, j = r >> 2, c = r & 3;
            int k = kb * 4 + c;
            sm[OFF_WPUT + idx] = (k < D2) ? WPu_w[j * D2 + k] : 0.0f;
        }
        const float* h0 = dir ? h0r : h0f;
        for (int idx = tid; idx < G * HP; idx += NTH) {
            int i = idx / HP, j = idx % HP;
            int b = (item0 + i) & 255;
            sm[OFF_H + idx] = (j < H) ? h0[b * H + j] : 0.0f;
            sm[OFF_V + idx] = (j < H) ? Vt[b * H + j] : 0.0f;
            sm[OFF_E + idx] = 0.0f;                   // zero incl. pad (p2 ghost term)
        }
        for (int idx = tid; idx < 2 * G * CCS; idx += NTH)   // zero CC + X (pads!)
            sm[OFF_CC + idx] = 0.0f;
        for (int idx = tid; idx < G * LQ * QPS; idx += NTH) { // Qproj fp16, stride 76
            int i = idx / (LQ * QPS);
            int r = idx - i * (LQ * QPS);
            int q = r / QPS, j = r - q * QPS;
            int b = (item0 + i) & 255;
            smh[idx] = (j < H) ? g_QprojH[((size_t)q * NB + b) * H + j]
                               : __float2half(0.0f);
        }
        // p(0)
        int te0 = dir ? (LP - 1) : 0;
        for (int idx = tid; idx < G * D2; idx += NTH) {
            int i = idx / D2, d = idx - i * D2;
            int b = (item0 + i) & 255;
            sm[OFF_CC + i * CCS + d] = passEnc[((size_t)te0 * NB + b) * D2 + d];
        }
    }

    // ---- hoisted per-thread constants ----
    const int i1 = tid / H, j1 = tid % H;
    const bool p1_act = (tid < G * H);
    const float b_ph1 = p1_act ? (WPu_b[j1] + WPv_b[j1]) : 0.0f;

    const int half = tid & 1, pair = tid >> 1;            // p2: 2 threads / (i,q)
    const int i2 = pair >> 6, q2 = pair & 63;
    const __half2* qp2 = reinterpret_cast<const __half2*>(smh + i2 * (LQ * QPS) + q2 * QPS)
                         + (half ? 19 : 0);
    const float2* ee2 = reinterpret_cast<const float2*>(sm + OFF_E + i2 * HP) + (half ? 19 : 0);
    const float2* vv2 = reinterpret_cast<const float2*>(sm + OFF_V + i2 * HP) + (half ? 19 : 0);

    const float b_g  = (tid < H4) ? Wg_b[tid] : 0.0f;

    // p6 pair-split: tid < 450: j6 = tid>>1, kh = tid&1
    const int j6 = tid >> 1, kh = tid & 1;
    const bool p6_act = (tid < 2 * H3);
    const float b_ih = p6_act ? (dir ? bih_r : bih_f)[j6] : 0.0f;
    const unsigned shmask = (tid >= 448) ? 0x3u : 0xFFFFFFFFu;
    const float* bhh_d = dir ? bhh_r : bhh_f;

    const uint4* wg_base = reinterpret_cast<const uint4*>(g_Wg4h) + tid;
    const uint4* wi_all  = reinterpret_cast<const uint4*>(g_Wih4h[dir]);

    const ull* x0c = reinterpret_cast<const ull*>(sm + OFF_CC);
    const ull* x1c = reinterpret_cast<const ull*>(sm + OFF_CC + CCS);
    const ull* x2c = reinterpret_cast<const ull*>(sm + OFF_CC + 2 * CCS);
    const ull* x3c = reinterpret_cast<const ull*>(sm + OFF_CC + 3 * CCS);
    const ull* x0x = reinterpret_cast<const ull*>(sm + OFF_X);
    const ull* x1x = reinterpret_cast<const ull*>(sm + OFF_X + CCS);
    const ull* x2x = reinterpret_cast<const ull*>(sm + OFF_X + 2 * CCS);
    const ull* x3x = reinterpret_cast<const ull*>(sm + OFF_X + 3 * CCS);
    const ull* hh0 = reinterpret_cast<const ull*>(sm + OFF_H);
    const ull* hh1 = reinterpret_cast<const ull*>(sm + OFF_H + HP);
    const ull* hh2 = reinterpret_cast<const ull*>(sm + OFF_H + 2 * HP);
    const ull* hh3 = reinterpret_cast<const ull*>(sm + OFF_H + 3 * HP);

    __syncthreads();

#define LD2(p, idx) (*reinterpret_cast<const ulonglong2*>((p) + (idx)))

    // ================= main 500-step loop =================
    for (int t = 0; t < LP; t++) {
        float pf0 = 0.0f, pf1 = 0.0f, pf2 = 0.0f;   // p(t+1) prefetch regs

        // ---- phase 1: e = WPu@p + WPv@h  ||  gh = h@Whh.T + bhh ----
        if (p1_act) {
            ull aA = pack2(b_ph1, 0.0f), aB = 0ull;
            const ulonglong2* wpu = reinterpret_cast<const ulonglong2*>(sm + OFF_WPUT);
            const ulonglong2* wpv = reinterpret_cast<const ulonglong2*>(sm + OFF_WPVT);
            const ull* pp = (i1 == 0) ? x0c : (i1 == 1) ? x1c : (i1 == 2) ? x2c : x3c;
            const ull* hh = (i1 == 0) ? hh0 : (i1 == 1) ? hh1 : (i1 == 2) ? hh2 : hh3;
#pragma unroll 19
            for (int kb = 0; kb < 38; kb++) {
                ulonglong2 w = wpu[kb * H + j1];
                ulonglong2 a = LD2(pp, 2 * kb);
                fma2(aA, w.x, a.x); fma2(aB, w.y, a.y);
            }
#pragma unroll 19
            for (int kb = 0; kb < 19; kb++) {
                ulonglong2 w = wpv[kb * H + j1];
                ulonglong2 a = LD2(hh, 2 * kb);
                fma2(aA, w.x, a.x); fma2(aB, w.y, a.y);
            }
            sm[OFF_E + i1 * HP + j1] = hsum2(aA) + hsum2(aB);
        } else {
            const ulonglong2* whh = reinterpret_cast<const ulonglong2*>(sm + OFF_WHHT);
            for (int rr = tid - 300; rr < H3; rr += 212) {
                ull a0A = 0, a0B = 0, a1A = 0, a1B = 0;
                ull a2A = 0, a2B = 0, a3A = 0, a3B = 0;
#pragma unroll 19
                for (int kb = 0; kb < 19; kb++) {
                    ulonglong2 w = whh[kb * H3 + rr];
                    ulonglong2 v0 = LD2(hh0, 2 * kb), v1 = LD2(hh1, 2 * kb);
                    ulonglong2 v2 = LD2(hh2, 2 * kb), v3 = LD2(hh3, 2 * kb);
                    fma2(a0A, w.x, v0.x); fma2(a0B, w.y, v0.y);
                    fma2(a1A, w.x, v1.x); fma2(a1B, w.y, v1.y);
                    fma2(a2A, w.x, v2.x); fma2(a2B, w.y, v2.y);
                    fma2(a3A, w.x, v3.x); fma2(a3B, w.y, v3.y);
                }
                float bb = bhh_d[rr];
                sm[OFF_GH + 0 * GIS + rr] = hsum2(a0A) + hsum2(a0B) + bb;
                sm[OFF_GH + 1 * GIS + rr] = hsum2(a1A) + hsum2(a1B) + bb;
                sm[OFF_GH + 2 * GIS + rr] = hsum2(a2A) + hsum2(a2B) + bb;
                sm[OFF_GH + 3 * GIS + rr] = hsum2(a3A) + hsum2(a3B) + bb;
            }
        }
        __syncthreads();

        // ---- phase 2: attention scores (fixed 19x2, ghost term j=75 -> v=0) ----
        {
            const float* vvs = sm + OFF_V + i2 * HP;  (void)vvs;
            float acc = 0.0f;
#pragma unroll
            for (int u = 0; u < 19; u++) {
                float2 qp = __half22float2(qp2[u]);
                float2 e = ee2[u], v = vv2[u];
                acc = fmaf(tanha(qp.x + e.x), v.x, acc);
                acc = fmaf(tanha(qp.y + e.y), v.y, acc);
            }
            sm[OFF_PART + half * (G * LQ) + i2 * LQ + q2] = acc;
        }
        __syncthreads();

        // ---- phase 3: softmax ----
        {
            int wid = tid >> 5, lane = tid & 31;
            if (wid < G) {
                float v0 = sm[OFF_PART + wid * LQ + lane]      + sm[OFF_PART + G * LQ + wid * LQ + lane];
                float v1 = sm[OFF_PART + wid * LQ + lane + 32] + sm[OFF_PART + G * LQ + wid * LQ + lane + 32];
                float m = fmaxf(v0, v1);
#pragma unroll
                for (int o = 16; o > 0; o >>= 1) m = fmaxf(m, __shfl_xor_sync(0xffffffffu, m, o));
                float e0 = __expf(v0 - m), e1 = __expf(v1 - m);
                float s = e0 + e1;
#pragma unroll
                for (int o = 16; o > 0; o >>= 1) s += __shfl_xor_sync(0xffffffffu, s, o);
                float inv = __fdividef(1.0f, s);
                sm[OFF_S + wid * LQ + lane]      = e0 * inv;
                sm[OFF_S + wid * LQ + lane + 32] = e1 * inv;
            }
        }
        __syncthreads();

        // ---- phase 4: context c -> cc[150..300) (float2, 300 threads) ----
        if (tid < G * 75) {
            int i = tid / 75, d2 = tid % 75;
            int b = (item0 + i) & 255;
            const float2* qe2 = reinterpret_cast<const float2*>(quesEnc + (size_t)b * D2) + d2;
            const float4* a4 = reinterpret_cast<const float4*>(sm + OFF_S + i * LQ);
            float ax = 0.0f, ay = 0.0f;
#pragma unroll
            for (int q4 = 0; q4 < 16; q4++) {
                float4 av = a4[q4];
                float2 v0 = qe2[(4 * q4 + 0) * (NB * 75)];
                float2 v1 = qe2[(4 * q4 + 1) * (NB * 75)];
                float2 v2 = qe2[(4 * q4 + 2) * (NB * 75)];
                float2 v3 = qe2[(4 * q4 + 3) * (NB * 75)];
                ax = fmaf(av.x, v0.x, ax); ay = fmaf(av.x, v0.y, ay);
                ax = fmaf(av.y, v1.x, ax); ay = fmaf(av.y, v1.y, ay);
                ax = fmaf(av.z, v2.x, ax); ay = fmaf(av.z, v2.y, ay);
                ax = fmaf(av.w, v3.x, ax); ay = fmaf(av.w, v3.y, ay);
            }
            reinterpret_cast<float2*>(sm + OFF_CC + i * CCS)[75 + d2] = make_float2(ax, ay);
        }
        __syncthreads();

        // ---- phase 5: x = sigmoid(Wg@cc + b)*cc (fp16 stream) || prefetch p(t+1) ----
        if (tid < H4) {
            ull a0A = 0, a0B = 0, a1A = 0, a1B = 0;
            ull a2A = 0, a2B = 0, a3A = 0, a3B = 0;
#pragma unroll 19
            for (int kb = 0; kb < KB8; kb++) {
                uint4 w = wg_base[kb * H4];
                ull w0 = h2f2(w.x), w1 = h2f2(w.y), w2 = h2f2(w.z), w3 = h2f2(w.w);
                ulonglong2 pa, pb;
                pa = LD2(x0c, 4 * kb); pb = LD2(x0c, 4 * kb + 2);
                fma2(a0A, w0, pa.x); fma2(a0B, w1, pa.y);
                fma2(a0A, w2, pb.x); fma2(a0B, w3, pb.y);
                pa = LD2(x1c, 4 * kb); pb = LD2(x1c, 4 * kb + 2);
                fma2(a1A, w0, pa.x); fma2(a1B, w1, pa.y);
                fma2(a1A, w2, pb.x); fma2(a1B, w3, pb.y);
                pa = LD2(x2c, 4 * kb); pb = LD2(x2c, 4 * kb + 2);
                fma2(a2A, w0, pa.x); fma2(a2B, w1, pa.y);
                fma2(a2A, w2, pb.x); fma2(a2B, w3, pb.y);
                pa = LD2(x3c, 4 * kb); pb = LD2(x3c, 4 * kb + 2);
                fma2(a3A, w0, pa.x); fma2(a3B, w1, pa.y);
                fma2(a3A, w2, pb.x); fma2(a3B, w3, pb.y);
            }
            int j = tid;
            sm[OFF_X + 0 * CCS + j] = siga(hsum2(a0A) + hsum2(a0B) + b_g) * sm[OFF_CC + 0 * CCS + j];
            sm[OFF_X + 1 * CCS + j] = siga(hsum2(a1A) + hsum2(a1B) + b_g) * sm[OFF_CC + 1 * CCS + j];
            sm[OFF_X + 2 * CCS + j] = siga(hsum2(a2A) + hsum2(a2B) + b_g) * sm[OFF_CC + 2 * CCS + j];
            sm[OFF_X + 3 * CCS + j] = siga(hsum2(a3A) + hsum2(a3B) + b_g) * sm[OFF_CC + 3 * CCS + j];
        } else if (tid >= 308 && tid < 508) {
            int u = tid - 308;
            int tn = (t + 1 < LP) ? t + 1 : t;
            int ten = dir ? (LP - 1 - tn) : tn;
#pragma unroll
            for (int c = 0; c < 3; c++) {
                int e = 3 * u + c;
                int i = e / D2, d = e - i * D2;
                int b = (item0 + i) & 255;
                float v = passEnc[((size_t)ten * NB + b) * D2 + d];
                if (c == 0) pf0 = v; else if (c == 1) pf1 = v; else pf2 = v;
            }
        }
        __syncthreads();

        // ---- phase 6: gi = Wih@x + bih (pair-split k, shfl combine) ----
        if (p6_act) {
            ull a0A = 0, a0B = 0, a1A = 0, a1B = 0;
            ull a2A = 0, a2B = 0, a3A = 0, a3B = 0;
            const int kb0 = kh * 19;
#pragma unroll 19
            for (int kk = 0; kk < 19; kk++) {
                int kb = kb0 + kk;
                uint4 w = wi_all[kb * H3 + j6];
                ull w0 = h2f2(w.x), w1 = h2f2(w.y), w2 = h2f2(w.z), w3 = h2f2(w.w);
                ulonglong2 pa, pb;
                pa = LD2(x0x, 4 * kb); pb = LD2(x0x, 4 * kb + 2);
                fma2(a0A, w0, pa.x); fma2(a0B, w1, pa.y);
                fma2(a0A, w2, pb.x); fma2(a0B, w3, pb.y);
                pa = LD2(x1x, 4 * kb); pb = LD2(x1x, 4 * kb + 2);
                fma2(a1A, w0, pa.x); fma2(a1B, w1, pa.y);
                fma2(a1A, w2, pb.x); fma2(a1B, w3, pb.y);
                pa = LD2(x2x, 4 * kb); pb = LD2(x2x, 4 * kb + 2);
                fma2(a2A, w0, pa.x); fma2(a2B, w1, pa.y);
                fma2(a2A, w2, pb.x); fma2(a2B, w3, pb.y);
                pa = LD2(x3x, 4 * kb); pb = LD2(x3x, 4 * kb + 2);
                fma2(a3A, w0, pa.x); fma2(a3B, w1, pa.y);
                fma2(a3A, w2, pb.x); fma2(a3B, w3, pb.y);
            }
            float g0 = hsum2(a0A) + hsum2(a0B);
            float g1 = hsum2(a1A) + hsum2(a1B);
            float g2 = hsum2(a2A) + hsum2(a2B);
            float g3 = hsum2(a3A) + hsum2(a3B);
            g0 += __shfl_xor_sync(shmask, g0, 1);
            g1 += __shfl_xor_sync(shmask, g1, 1);
            g2 += __shfl_xor_sync(shmask, g2, 1);
            g3 += __shfl_xor_sync(shmask, g3, 1);
            if (kh == 0) {
                sm[OFF_GI + 0 * GIS + j6] = g0 + b_ih;
                sm[OFF_GI + 1 * GIS + j6] = g1 + b_ih;
                sm[OFF_GI + 2 * GIS + j6] = g2 + b_ih;
                sm[OFF_GI + 3 * GIS + j6] = g3 + b_ih;
            }
        }
        __syncthreads();

        // ---- phase 7: GRU combine + h/out write  ||  store p(t+1) ----
        if (tid < G * H) {
            int i = i1, j = j1;
            float gr  = sm[OFF_GI + i * GIS + j]         + sm[OFF_GH + i * GIS + j];
            float gz  = sm[OFF_GI + i * GIS + H + j]     + sm[OFF_GH + i * GIS + H + j];
            float gin = sm[OFF_GI + i * GIS + 2 * H + j];
            float ghn = sm[OFF_GH + i * GIS + 2 * H + j];
            float r = siga(gr);
            float z = siga(gz);
            float n = tanha(fmaf(r, ghn, gin));
            float hn = (1.0f - z) * n + z * sm[OFF_H + i * HP + j];
            sm[OFF_H + i * HP + j] = hn;
            int b = (item0 + i) & 255;
            out[((size_t)t * NB + b) * D2 + dir * H + j] = hn;
        } else if (tid >= 308 && tid < 508) {
            int u = tid - 308;
#pragma unroll
            for (int c = 0; c < 3; c++) {
                int e = 3 * u + c;
                int i = e / D2, d = e - i * D2;
                float v = (c == 0) ? pf0 : (c == 1) ? pf1 : pf2;
                sm[OFF_CC + i * CCS + d] = v;
            }
        }
        __syncthreads();
    }
#undef LD2
}

extern "C" void kernel_launch(void* const* d_in, const int* in_sizes, int n_in,
                              void* d_out, int out_size) {
    const float* quesEnc = (const float*)d_in[0];
    const float* passEnc = (const float*)d_in[1];
    const float* WQu_w   = (const float*)d_in[2];
    const float* WQu_b   = (const float*)d_in[3];
    const float* WPu_w   = (const float*)d_in[4];
    const float* WPu_b   = (const float*)d_in[5];
    const float* WPv_w   = (const float*)d_in[6];
    const float* WPv_b   = (const float*)d_in[7];
    const float* Wg_w    = (const float*)d_in[8];
    const float* Wg_b    = (const float*)d_in[9];
    const float* Vt      = (const float*)d_in[10];
    const float* Wih_f   = (const float*)d_in[11];
    const float* Whh_f   = (const float*)d_in[12];
    const float* bih_f   = (const float*)d_in[13];
    const float* bhh_f   = (const float*)d_in[14];
    const float* Wih_r   = (const float*)d_in[15];
    const float* Whh_r   = (const float*)d_in[16];
    const float* bih_r   = (const float*)d_in[17];
    const float* bhh_r   = (const float*)d_in[18];
    const float* h0f     = (const float*)d_in[19];
    const float* h0r     = (const float*)d_in[20];
    float* out = (float*)d_out;

    cudaFuncSetAttribute(persist_kernel,
                         cudaFuncAttributeMaxDynamicSharedMemorySize, SMEM_BYTES);

    prep_kernel<<<(PREP_N + 255) / 256, 256>>>(WQu_w, Wg_w, Wih_f, Wih_r);
    qproj_kernel<<<(LQ * NB * H + 255) / 256, 256>>>(quesEnc, WQu_b);
    persist_kernel<<<NBLK, NTH, SMEM_BYTES>>>(quesEnc, passEnc,
                                              WPu_w, WPu_b, WPv_w, WPv_b,
                                              Wg_b, Vt,
                                              Whh_f, bih_f, bhh_f,
                                              Whh_r, bih_r, bhh_r,
                                              h0f, h0r, out);
}